// round 14
// baseline (speedup 1.0000x reference)
#include <cuda_runtime.h>
#include <cuda_fp16.h>
#include <cstdint>

namespace {
constexpr int B = 16;
constexpr int L = 1024;
constexpr int H = 512;
constexpr int V = 32000;
constexpr int HALF = 256;
constexpr int TOK = B * L;           // 16384
constexpr float ALPHA_C = 0.05f;     // 1 - 0.95
constexpr float EPS_LN_C = 1e-5f;
constexpr float EPS_NORM_C = 1e-12f;

// GEMM tiling (fp16 operands, fp32 accum)
constexpr int TM = 128;
constexpr int TN = 128;
constexpr int TKH = 64;              // halves per k-tile = 128 bytes per row
constexpr int STG = 3;               // cp.async stages
constexpr int TILE_BYTES = 128 * 128;            // 16 KB per matrix per stage
constexpr int SMEM_H = STG * 2 * TILE_BYTES;     // 96 KB

// scan blocking
constexpr int NBLK = 127;            // 127*8 + 7 remainder = 1023 steps
constexpr int GSZ = 36;              // 28 pair-grams + 8 inv-norms per block

// logits tensor kernel
constexpr int ONT = 256;             // v-columns per CTA
constexpr int RS_STRIDE = 520;       // padded r row stride (halves) -> conflict-free ldsm
constexpr int WT_OFF = 17408;        // W tiles start (1024-aligned, after 16640B r_s)
constexpr int WT_TILE = 256 * 128;   // 32 KB per stage
constexpr int SMEM_OUT = WT_OFF + 3 * WT_TILE;   // 115712 B
}

// ---------------- scratch (static device globals; no allocation) ----------------
__device__ __half g_h0h[TOK * H];            // embed gather output (fp16)
__device__ __half g_ff1h[TOK * 2 * H];       // FFN hidden (fp16)
__device__ __half g_y2h[TOK * H];            // FFN output (pre-LN, fp16)
__device__ __half g_hh[TOK * H];             // post-LN hidden (fp16)
__device__ float  g_kn[2 * L * B * HALF];    // RAW keys [m][l][b][i]
__device__ float  g_gram[32 * NBLK * GSZ];   // precomputed grams+inv-norms
__device__ float  g_c[B * H];                // context
__device__ float  g_r[B * H];                // readout projection
__device__ __half g_w1h[2 * H * H];          // fp16 ff_w1
__device__ __half g_w2h[2 * H * H];          // fp16 ff_w2
__device__ __half g_wch[2 * HALF * H];       // fp16 [sem_w ; epi_w]
__device__ __half g_owh[(size_t)V * H];      // fp16 out_w

// ---------------- helpers ----------------
__device__ __forceinline__ uint32_t smem_u32(const void* p) {
    return (uint32_t)__cvta_generic_to_shared(p);
}
__device__ __forceinline__ void cp16(uint32_t dst, const void* src) {
    asm volatile("cp.async.cg.shared.global [%0], [%1], 16;" :: "r"(dst), "l"(src));
}
__device__ __forceinline__ uint32_t sw128(uint32_t off) {
    return off ^ ((off >> 3) & 0x70u);
}
__device__ __forceinline__ void ldsm_x4(uint32_t& r0, uint32_t& r1, uint32_t& r2,
                                        uint32_t& r3, uint32_t a) {
    asm volatile("ldmatrix.sync.aligned.m8n8.x4.shared.b16 {%0,%1,%2,%3}, [%4];"
                 : "=r"(r0), "=r"(r1), "=r"(r2), "=r"(r3) : "r"(a));
}
__device__ __forceinline__ void ldsm_x2(uint32_t& r0, uint32_t& r1, uint32_t a) {
    asm volatile("ldmatrix.sync.aligned.m8n8.x2.shared.b16 {%0,%1}, [%2];"
                 : "=r"(r0), "=r"(r1) : "r"(a));
}
__device__ __forceinline__ void mma_f16(float* d, const uint32_t* a, const uint32_t* b) {
    asm volatile(
        "mma.sync.aligned.m16n8k16.row.col.f32.f16.f16.f32 "
        "{%0,%1,%2,%3},{%4,%5,%6,%7},{%8,%9},{%0,%1,%2,%3};"
        : "+f"(d[0]), "+f"(d[1]), "+f"(d[2]), "+f"(d[3])
        : "r"(a[0]), "r"(a[1]), "r"(a[2]), "r"(a[3]), "r"(b[0]), "r"(b[1]));
}

// ---------------- weight conversions ----------------
__global__ void k_round_w1(const float* __restrict__ w1, __half* __restrict__ d1) {
    int i = blockIdx.x * 256 + threadIdx.x;
    float4 v = __ldg(reinterpret_cast<const float4*>(w1) + i);
    __half2* d = reinterpret_cast<__half2*>(d1) + i * 2;
    d[0] = __floats2half2_rn(v.x, v.y);
    d[1] = __floats2half2_rn(v.z, v.w);
}

// blocks [0,512): ff_w2 ; [512,640): sem ; [640,768): epi ; [768,16768): out_w
__global__ void k_round_rest(const float* __restrict__ w2,
                             const float* __restrict__ sem, const float* __restrict__ epi,
                             const float* __restrict__ ow,
                             __half* __restrict__ d2, __half* __restrict__ dc,
                             __half* __restrict__ dow) {
    int blk = blockIdx.x;
    const float* src;
    __half* dst;
    int base;
    if (blk < 512)      { src = w2;  dst = d2; base = blk; }
    else if (blk < 640) { src = sem; dst = dc; base = blk - 512; }
    else if (blk < 768) { src = epi; dst = dc + (size_t)HALF * H; base = blk - 640; }
    else                { src = ow;  dst = dow; base = blk - 768; }
    size_t i = (size_t)base * 256 + threadIdx.x;
    float4 v = __ldg(reinterpret_cast<const float4*>(src) + i);
    __half2* d = reinterpret_cast<__half2*>(dst) + i * 2;
    d[0] = __floats2half2_rn(v.x, v.y);
    d[1] = __floats2half2_rn(v.z, v.w);
}

// ---------------- embedding gather (fp16 out) ----------------
__global__ void k_gather(const int* __restrict__ seq, const float* __restrict__ embed,
                         __half* __restrict__ out) {
    int t = blockIdx.x;
    int v = seq[t];
    const float4* src = reinterpret_cast<const float4*>(embed + (size_t)v * H);
    float4 x = src[threadIdx.x];
    __half2* dst = reinterpret_cast<__half2*>(out + (size_t)t * H) + threadIdx.x * 2;
    dst[0] = __floats2half2_rn(x.x, x.y);
    dst[1] = __floats2half2_rn(x.z, x.w);
}

// ---------------- fp16 tensor GEMM ----------------
// MODE 0: +bias -> fp16; MODE 1: +bias+relu -> fp16; MODE 2: raw fp32 scatter [l][b][c]
template <int MODE>
__global__ void __launch_bounds__(256) k_gemm(const __half* __restrict__ A,
                                              const __half* __restrict__ W,
                                              const float* __restrict__ bias,
                                              void* __restrict__ Cv,
                                              int N, int K) {
    extern __shared__ char smem[];
    const uint32_t sb = smem_u32(smem);
    uint32_t a_off[STG], w_off[STG];
#pragma unroll
    for (int s = 0; s < STG; ++s) {
        a_off[s] = s * 2 * TILE_BYTES;
        w_off[s] = s * 2 * TILE_BYTES + TILE_BYTES;
    }

    const int tid = threadIdx.x;
    const int bm = blockIdx.y * TM;
    const int bn = blockIdx.x * TN;
    const int warp = tid >> 5, lane = tid & 31;
    const int wm = warp >> 2, wn = warp & 3;
    const int g = lane >> 2, tg = lane & 3;

    const int row = tid >> 1;
    const int h64 = tid & 1;
    const __half* Ag = A + (size_t)(bm + row) * K + h64 * 32;
    const __half* Wg = W + (size_t)(bn + row) * K + h64 * 32;
    uint32_t swz[4];
#pragma unroll
    for (int c = 0; c < 4; ++c) swz[c] = sw128(row * 128 + h64 * 64 + c * 16);

    float acc[4][4][4];
#pragma unroll
    for (int mi = 0; mi < 4; ++mi)
#pragma unroll
        for (int ni = 0; ni < 4; ++ni)
#pragma unroll
            for (int q = 0; q < 4; ++q) acc[mi][ni][q] = 0.f;

    auto issue_tile = [&](int st, int kt) {
#pragma unroll
        for (int c = 0; c < 4; ++c)
            cp16(sb + a_off[st] + swz[c], Ag + (size_t)kt * TKH + c * 8);
#pragma unroll
        for (int c = 0; c < 4; ++c)
            cp16(sb + w_off[st] + swz[c], Wg + (size_t)kt * TKH + c * 8);
        asm volatile("cp.async.commit_group;" ::: "memory");
    };

    const int a_r = lane & 15;
    const int a_cb = (lane >> 4) * 16;
    const int b_r = lane & 7;
    const int b_cb = ((lane >> 3) & 1) * 16;

    auto mma_pass = [&](int buf) {
#pragma unroll
        for (int ak = 0; ak < 4; ++ak) {
            const int kb = ak * 32;
            uint32_t afrag[4][4];
#pragma unroll
            for (int mi = 0; mi < 4; ++mi) {
                uint32_t addr = sb + a_off[buf] +
                    sw128((uint32_t)(wm * 64 + mi * 16 + a_r) * 128 + kb + a_cb);
                ldsm_x4(afrag[mi][0], afrag[mi][1], afrag[mi][2], afrag[mi][3], addr);
            }
            uint32_t bfrag[4][2];
#pragma unroll
            for (int ni = 0; ni < 4; ++ni) {
                uint32_t addr = sb + w_off[buf] +
                    sw128((uint32_t)(wn * 32 + ni * 8 + b_r) * 128 + kb + b_cb);
                ldsm_x2(bfrag[ni][0], bfrag[ni][1], addr);
            }
#pragma unroll
            for (int mi = 0; mi < 4; ++mi)
#pragma unroll
                for (int ni = 0; ni < 4; ++ni)
                    mma_f16(acc[mi][ni], afrag[mi], bfrag[ni]);
        }
    };

    const int NPASS = K / TKH;
    issue_tile(0, 0);
    issue_tile(1, 1);

    int p = 0;
    for (; p < NPASS - 1; ++p) {
        asm volatile("cp.async.wait_group 1;" ::: "memory");
        __syncthreads();
        if (p + 2 < NPASS) issue_tile((p + 2) % STG, p + 2);
        mma_pass(p % STG);
    }
    asm volatile("cp.async.wait_group 0;" ::: "memory");
    __syncthreads();
    mma_pass(p % STG);

#pragma unroll
    for (int mi = 0; mi < 4; ++mi) {
#pragma unroll
        for (int half = 0; half < 2; ++half) {
            int r = bm + wm * 64 + mi * 16 + g + half * 8;
#pragma unroll
            for (int ni = 0; ni < 4; ++ni) {
                int col = bn + wn * 32 + ni * 8 + tg * 2;
                float x = acc[mi][ni][half * 2 + 0];
                float y = acc[mi][ni][half * 2 + 1];
                if (MODE == 2) {
                    int b_ = r >> 10, l_ = r & 1023;
                    float* dst = (float*)Cv + ((size_t)l_ * B + b_) * HALF + col;
                    *reinterpret_cast<float2*>(dst) = make_float2(x, y);
                } else {
                    x += bias[col];
                    y += bias[col + 1];
                    if (MODE == 1) { x = fmaxf(x, 0.f); y = fmaxf(y, 0.f); }
                    __half* dst = (__half*)Cv + (size_t)r * N + col;
                    *reinterpret_cast<__half2*>(dst) = __floats2half2_rn(x, y);
                }
            }
        }
    }
}

// ---------------- residual + LayerNorm (warp per row; fp16 in/out) ----------------
__global__ void k_ln(const __half* __restrict__ y2, const __half* __restrict__ h0,
                     const float* __restrict__ gamma, const float* __restrict__ beta,
                     __half* __restrict__ out) {
    int warp = threadIdx.x >> 5, lane = threadIdx.x & 31;
    int row = blockIdx.x * 8 + warp;
    const __half2* a = reinterpret_cast<const __half2*>(y2 + (size_t)row * H);
    const __half2* hb = reinterpret_cast<const __half2*>(h0 + (size_t)row * H);
    float x[16];
    float s = 0.f, s2 = 0.f;
#pragma unroll
    for (int i = 0; i < 4; ++i) {
        int idx = (lane + i * 32) * 2;
        float2 u0 = __half22float2(a[idx]);
        float2 u1 = __half22float2(a[idx + 1]);
        float2 v0 = __half22float2(hb[idx]);
        float2 v1 = __half22float2(hb[idx + 1]);
        float t0 = u0.x + v0.x, t1 = u0.y + v0.y, t2 = u1.x + v1.x, t3 = u1.y + v1.y;
        x[i * 4 + 0] = t0; x[i * 4 + 1] = t1; x[i * 4 + 2] = t2; x[i * 4 + 3] = t3;
        s += t0 + t1 + t2 + t3;
        s2 += t0 * t0 + t1 * t1 + t2 * t2 + t3 * t3;
    }
#pragma unroll
    for (int off = 16; off > 0; off >>= 1) {
        s += __shfl_xor_sync(0xffffffffu, s, off);
        s2 += __shfl_xor_sync(0xffffffffu, s2, off);
    }
    float mu = s * (1.f / H);
    float var = s2 * (1.f / H) - mu * mu;
    float rstd = rsqrtf(var + EPS_LN_C);
    __half2* o = reinterpret_cast<__half2*>(out + (size_t)row * H);
    const float4* g4 = reinterpret_cast<const float4*>(gamma);
    const float4* b4 = reinterpret_cast<const float4*>(beta);
#pragma unroll
    for (int i = 0; i < 4; ++i) {
        float4 gg = __ldg(g4 + lane + i * 32);
        float4 bb = __ldg(b4 + lane + i * 32);
        float r0 = (x[i * 4 + 0] - mu) * rstd * gg.x + bb.x;
        float r1 = (x[i * 4 + 1] - mu) * rstd * gg.y + bb.y;
        float r2 = (x[i * 4 + 2] - mu) * rstd * gg.z + bb.z;
        float r3 = (x[i * 4 + 3] - mu) * rstd * gg.w + bb.w;
        o[(lane + i * 32) * 2] = __floats2half2_rn(r0, r1);
        o[(lane + i * 32) * 2 + 1] = __floats2half2_rn(r2, r3);
    }
}

// ---------------- Gram precompute (per m-half): one warp per (b,kblk) --------
__global__ void __launch_bounds__(32) k_gram(const float* __restrict__ kn_m,
                                             float* __restrict__ gram_m) {
    const int bx = blockIdx.x;
    const int b = bx / NBLK;
    const int kblk = bx - b * NBLK;
    const int lane = threadIdx.x;
    const float* kn = kn_m + b * HALF;
    const int t0 = 7 + 8 * kblk;
    const int STRD = B * HALF;

    float k8[8][8];
#pragma unroll
    for (int j = 0; j < 8; ++j) {
        const float4* p = reinterpret_cast<const float4*>(
            kn + (size_t)(t0 + j) * STRD + lane * 8);
        float4 u = __ldg(p), w = __ldg(p + 1);
        k8[j][0] = u.x; k8[j][1] = u.y; k8[j][2] = u.z; k8[j][3] = u.w;
        k8[j][4] = w.x; k8[j][5] = w.y; k8[j][6] = w.z; k8[j][7] = w.w;
    }
    float red[GSZ];
#pragma unroll
    for (int q = 0; q < GSZ; ++q) red[q] = 0.f;
#pragma unroll
    for (int e = 0; e < 8; ++e) {
        int p = 0;
#pragma unroll
        for (int j = 0; j < 8; ++j) {
#pragma unroll
            for (int i = j + 1; i < 8; ++i) {
                red[p] += k8[j][e] * k8[i][e];
                ++p;
            }
        }
#pragma unroll
        for (int j = 0; j < 8; ++j) red[28 + j] += k8[j][e] * k8[j][e];
    }
#pragma unroll
    for (int off = 16; off > 0; off >>= 1)
#pragma unroll
        for (int q = 0; q < GSZ; ++q)
            red[q] += __shfl_xor_sync(0xffffffffu, red[q], off);

    if (lane == 0) {
        float iv[8];
#pragma unroll
        for (int j = 0; j < 8; ++j)
            iv[j] = 1.f / fmaxf(sqrtf(red[28 + j]), EPS_NORM_C);
        float o[GSZ];
        int p = 0;
#pragma unroll
        for (int j = 0; j < 8; ++j)
#pragma unroll
            for (int i = j + 1; i < 8; ++i) {
                o[p] = ALPHA_C * red[p] * iv[j] * iv[i];
                ++p;
            }
#pragma unroll
        for (int j = 0; j < 8; ++j) o[28 + j] = iv[j];
        float4* dst = reinterpret_cast<float4*>(gram_m + (size_t)bx * GSZ);
#pragma unroll
        for (int q = 0; q < 9; ++q)
            dst[q] = make_float4(o[q * 4], o[q * 4 + 1], o[q * 4 + 2], o[q * 4 + 3]);
    }
}

// ---------------- EMA scan (per m-half): 8-step blocks, 2 warps per chain ----
// 64 threads; warp w owns elements [w*128, w*128+128), 4 floats per lane.
// Cross-warp dot combine via phase-toggled smem buffer, one barrier per block.
#define GP(j, i) gb[(j) * 7 - (j) * ((j) - 1) / 2 + (i) - (j) - 1]

__global__ void __launch_bounds__(64) k_scan(const float* __restrict__ kn_m,
                                             const float* __restrict__ gram_m,
                                             float* __restrict__ cbuf, int moff) {
    const int tid = threadIdx.x;
    const int w = tid >> 5, lane = tid & 31;
    const int b = blockIdx.x;
    const float* kn = kn_m + b * HALF;
    const int STRD = B * HALF;
    const int eoff = w * 128 + lane * 4;     // this thread's element offset

    __shared__ float stg[3][2048 + 64];
    __shared__ float red[2][2][8];           // [phase][warp][dot]
    __shared__ float red2[2][2][2];          // remainder steps: [phase][warp][du,dg]

    auto prefetch = [&](int st, int kblk) {
        int t0 = 7 + 8 * kblk;
        // keys: 8 rows x 1024B; 64 threads x 8 cp16 each
        int j = tid >> 3;                    // row 0..7
        int c0 = (tid & 7) * 8;              // cp16 index within row
#pragma unroll
        for (int c = 0; c < 8; ++c) {
            const float* src = kn + (size_t)(t0 + j) * STRD + (c0 + c) * 4;
            cp16(smem_u32(&stg[st][j * 256 + (c0 + c) * 4]), src);
        }
        if (tid < 9)
            cp16(smem_u32(&stg[st][2048 + tid * 4]),
                 gram_m + (size_t)(b * NBLK + kblk) * GSZ + tid * 4);
        asm volatile("cp.async.commit_group;" ::: "memory");
    };

    float v[4], cac[4];
    {
        const float4* p = reinterpret_cast<const float4*>(
            kn + (size_t)(L - 1) * STRD + eoff);
        float4 u = __ldg(p);
        v[0] = u.x; v[1] = u.y; v[2] = u.z; v[3] = u.w;
    }
#pragma unroll
    for (int j = 0; j < 4; ++j) cac[j] = 0.f;

    prefetch(0, NBLK - 1);
    prefetch(1, NBLK - 2);
    prefetch(2, NBLK - 3);

    for (int it = 0; it < NBLK; ++it) {
        int st = it % 3;
        int ph = it & 1;
        asm volatile("cp.async.wait_group 2;" ::: "memory");
        __syncthreads();                      // stage ready for both warps
        float cur[8][4];
#pragma unroll
        for (int j = 0; j < 8; ++j) {
            float4 u = *reinterpret_cast<const float4*>(&stg[st][j * 256 + eoff]);
            cur[j][0] = u.x; cur[j][1] = u.y; cur[j][2] = u.z; cur[j][3] = u.w;
        }
        float gb[GSZ];
#pragma unroll
        for (int q = 0; q < 9; ++q) {
            float4 t = *reinterpret_cast<const float4*>(&stg[st][2048 + q * 4]);
            gb[q * 4] = t.x; gb[q * 4 + 1] = t.y; gb[q * 4 + 2] = t.z; gb[q * 4 + 3] = t.w;
        }
        if (it + 3 < NBLK) prefetch(st, NBLK - 1 - (it + 3));

        // partial dots over this thread's 4 elements
        float u[8];
#pragma unroll
        for (int j = 0; j < 8; ++j)
            u[j] = cur[j][0] * v[0] + cur[j][1] * v[1] + cur[j][2] * v[2] + cur[j][3] * v[3];
#pragma unroll
        for (int off = 16; off > 0; off >>= 1)
#pragma unroll
            for (int j = 0; j < 8; ++j)
                u[j] += __shfl_xor_sync(0xffffffffu, u[j], off);
        if (lane < 8) red[ph][w][lane] = u[lane];
        __syncthreads();                      // combine across warps
#pragma unroll
        for (int j = 0; j < 8; ++j)
            u[j] = red[ph][0][j] + red[ph][1][j];

        float s7 = gb[35] * u[7];
        float s6 = gb[34] * u[6] - GP(6, 7) * s7;
        float s5 = gb[33] * u[5] - GP(5, 7) * s7 - GP(5, 6) * s6;
        float s4 = gb[32] * u[4] - GP(4, 7) * s7 - GP(4, 6) * s6 - GP(4, 5) * s5;
        float s3 = gb[31] * u[3] - GP(3, 7) * s7 - GP(3, 6) * s6 - GP(3, 5) * s5
                 - GP(3, 4) * s4;
        float s2 = gb[30] * u[2] - GP(2, 7) * s7 - GP(2, 6) * s6 - GP(2, 5) * s5
                 - GP(2, 4) * s4 - GP(2, 3) * s3;
        float s1 = gb[29] * u[1] - GP(1, 7) * s7 - GP(1, 6) * s6 - GP(1, 5) * s5
                 - GP(1, 4) * s4 - GP(1, 3) * s3 - GP(1, 2) * s2;
        float s0 = gb[28] * u[0] - GP(0, 7) * s7 - GP(0, 6) * s6 - GP(0, 5) * s5
                 - GP(0, 4) * s4 - GP(0, 3) * s3 - GP(0, 2) * s2 - GP(0, 1) * s1;

        float a0 = ALPHA_C * gb[28] * s0, a1 = ALPHA_C * gb[29] * s1;
        float a2 = ALPHA_C * gb[30] * s2, a3 = ALPHA_C * gb[31] * s3;
        float a4 = ALPHA_C * gb[32] * s4, a5 = ALPHA_C * gb[33] * s5;
        float a6 = ALPHA_C * gb[34] * s6, a7 = ALPHA_C * gb[35] * s7;

#pragma unroll
        for (int e = 0; e < 4; ++e) {
            float dv = cur[0][e] * a0 + cur[1][e] * a1 + cur[2][e] * a2 + cur[3][e] * a3
                     + cur[4][e] * a4 + cur[5][e] * a5 + cur[6][e] * a6 + cur[7][e] * a7;
            float dc = cur[0][e] * s0 + cur[1][e] * s1 + cur[2][e] * s2 + cur[3][e] * s3
                     + cur[4][e] * s4 + cur[5][e] * s5 + cur[6][e] * s6 + cur[7][e] * s7;
            v[e] -= dv;
            cac[e] += dc;
        }
    }

    // remainder: t = 6 .. 0 single steps
    for (int t = 6; t >= 0; --t) {
        int ph = t & 1;
        float kt[4];
        const float4* p = reinterpret_cast<const float4*>(kn + (size_t)t * STRD + eoff);
        float4 u = __ldg(p);
        kt[0] = u.x; kt[1] = u.y; kt[2] = u.z; kt[3] = u.w;
        float du = kt[0] * v[0] + kt[1] * v[1] + kt[2] * v[2] + kt[3] * v[3];
        float dg = kt[0] * kt[0] + kt[1] * kt[1] + kt[2] * kt[2] + kt[3] * kt[3];
#pragma unroll
        for (int off = 16; off > 0; off >>= 1) {
            du += __shfl_xor_sync(0xffffffffu, du, off);
            dg += __shfl_xor_sync(0xffffffffu, dg, off);
        }
        if (lane == 0) { red2[ph][w][0] = du; red2[ph][w][1] = dg; }
        __syncthreads();
        du = red2[ph][0][0] + red2[ph][1][0];
        dg = red2[ph][0][1] + red2[ph][1][1];
        float inv = 1.f / fmaxf(sqrtf(dg), EPS_NORM_C);
        float s = du * inv;
        float av = ALPHA_C * inv * s;
#pragma unroll
        for (int j = 0; j < 4; ++j) {
            cac[j] += kt[j] * s;
            v[j] -= kt[j] * av;
        }
    }

    float* out = cbuf + b * H + moff + eoff;
    *reinterpret_cast<float4*>(out) = make_float4(
        ALPHA_C * cac[0], ALPHA_C * cac[1], ALPHA_C * cac[2], ALPHA_C * cac[3]);
}

// ---------------- r = c @ rp_w^T + rp_b ----------------
__global__ void k_rp(const float* __restrict__ c, const float* __restrict__ W,
                     const float* __restrict__ bias, float* __restrict__ r) {
    __shared__ float cs[B * (H + 1)];
    for (int i = threadIdx.x; i < B * H; i += 256) {
        int bb = i >> 9, hh = i & 511;
        cs[bb * (H + 1) + hh] = c[i];
    }
    __syncthreads();
    int g = blockIdx.x * 16 + (threadIdx.x >> 4);
    int b = threadIdx.x & 15;
    const float* w = W + (size_t)g * H;
    const float* cb = &cs[b * (H + 1)];
    float acc = 0.f;
    for (int h = 0; h < H; h += 4) {
        float4 wv = __ldg(reinterpret_cast<const float4*>(w + h));
        acc += cb[h] * wv.x + cb[h + 1] * wv.y + cb[h + 2] * wv.z + cb[h + 3] * wv.w;
    }
    r[b * H + g] = acc + bias[g];
}

// ---------------- logits via tensor cores ----------------
__global__ void __launch_bounds__(128) k_outt(const float* __restrict__ r,
                                              const __half* __restrict__ Wh,
                                              const float* __restrict__ bias,
                                              float* __restrict__ out) {
    extern __shared__ char smem[];
    __half* r_s = reinterpret_cast<__half*>(smem);
    const uint32_t sb = smem_u32(smem);
    const int tid = threadIdx.x;
    const int warp = tid >> 5, lane = tid & 31;
    const int bn = blockIdx.x * ONT;
    const int g = lane >> 2, tg = lane & 3;

#pragma unroll
    for (int j = 0; j < 16; ++j) {
        int f = tid + j * 128;
        float4 v = __ldg(reinterpret_cast<const float4*>(r) + f);
        int row = (f * 4) >> 9, col = (f * 4) & 511;
        __half2* d = reinterpret_cast<__half2*>(r_s + row * RS_STRIDE + col);
        d[0] = __floats2half2_rn(v.x, v.y);
        d[1] = __floats2half2_rn(v.z, v.w);
    }

    auto wtile = [&](int st, int kt) {
#pragma unroll
        for (int rr = 0; rr < 2; ++rr) {
            int row = rr * 128 + tid;
            const __half* s = Wh + (size_t)(bn + row) * H + kt * TKH;
            uint32_t base = sb + WT_OFF + st * WT_TILE;
#pragma unroll
            for (int c = 0; c < 8; ++c)
                cp16(base + sw128((uint32_t)row * 128 + c * 16), s + c * 8);
        }
        asm volatile("cp.async.commit_group;" ::: "memory");
    };

    float acc[8][4];
#pragma unroll
    for (int ni = 0; ni < 8; ++ni)
#pragma unroll
        for (int q = 0; q < 4; ++q) acc[ni][q] = 0.f;

    auto opass = [&](int buf, int kt) {
#pragma unroll
        for (int ak = 0; ak < 4; ++ak) {
            uint32_t af[4];
            uint32_t aaddr = sb + (uint32_t)((lane & 15) * RS_STRIDE * 2 +
                                             kt * 128 + ak * 32 + (lane >> 4) * 16);
            ldsm_x4(af[0], af[1], af[2], af[3], aaddr);
            uint32_t bf[8][2];
#pragma unroll
            for (int ni = 0; ni < 8; ++ni) {
                uint32_t addr = sb + WT_OFF + buf * WT_TILE +
                    sw128((uint32_t)(warp * 64 + ni * 8 + (lane & 7)) * 128 + ak * 32 +
                          ((lane >> 3) & 1) * 16);
                ldsm_x2(bf[ni][0], bf[ni][1], addr);
            }
#pragma unroll
            for (int ni = 0; ni < 8; ++ni)
                mma_f16(acc[ni], af, bf[ni]);
        }
    };

    const int NP = H / TKH;   // 8
    wtile(0, 0);
    wtile(1, 1);
    int p = 0;
    for (; p < NP - 1; ++p) {
        asm volatile("cp.async.wait_group 1;" ::: "memory");
        __syncthreads();
        if (p + 2 < NP) wtile((p + 2) % 3, p + 2);
        opass(p % 3, p);
    }
    asm volatile("cp.async.wait_group 0;" ::: "memory");
    __syncthreads();
    opass(p % 3, p);

#pragma unroll
    for (int ni = 0; ni < 8; ++ni) {
        int col = bn + warp * 64 + ni * 8 + tg * 2;
        float bx = __ldg(bias + col);
        float by = __ldg(bias + col + 1);
#pragma unroll
        for (int half = 0; half < 2; ++half) {
            int b = g + half * 8;
            float x = acc[ni][half * 2 + 0] + bx;
            float y = acc[ni][half * 2 + 1] + by;
            *reinterpret_cast<float2*>(out + (size_t)b * V + col) = make_float2(x, y);
        }
    }
}

// ---------------- launch (forked-stream graph; resources created once) -------
extern "C" void kernel_launch(void* const* d_in, const int* in_sizes, int n_in,
                              void* d_out, int out_size) {
    const int*   seq   = (const int*)d_in[0];
    const float* embed = (const float*)d_in[1];
    const float* ff_w1 = (const float*)d_in[2];
    const float* ff_b1 = (const float*)d_in[3];
    const float* ff_w2 = (const float*)d_in[4];
    const float* ff_b2 = (const float*)d_in[5];
    const float* gamma = (const float*)d_in[6];
    const float* beta  = (const float*)d_in[7];
    const float* sem_w = (const float*)d_in[8];
    const float* epi_w = (const float*)d_in[9];
    const float* rp_w  = (const float*)d_in[10];
    const float* rp_b  = (const float*)d_in[11];
    const float* out_w = (const float*)d_in[12];
    const float* out_b = (const float*)d_in[13];
    float* out = (float*)d_out;

    __half *h0h, *ff1h, *y2h, *hh, *w1h, *w2h, *wch, *owh;
    float *kn, *gr, *c, *r;
    cudaGetSymbolAddress((void**)&h0h,  g_h0h);
    cudaGetSymbolAddress((void**)&ff1h, g_ff1h);
    cudaGetSymbolAddress((void**)&y2h,  g_y2h);
    cudaGetSymbolAddress((void**)&hh,   g_hh);
    cudaGetSymbolAddress((void**)&kn,   g_kn);
    cudaGetSymbolAddress((void**)&gr,   g_gram);
    cudaGetSymbolAddress((void**)&c,    g_c);
    cudaGetSymbolAddress((void**)&r,    g_r);
    cudaGetSymbolAddress((void**)&w1h,  g_w1h);
    cudaGetSymbolAddress((void**)&w2h,  g_w2h);
    cudaGetSymbolAddress((void**)&wch,  g_wch);
    cudaGetSymbolAddress((void**)&owh,  g_owh);

    static cudaStream_t sA = nullptr, sB = nullptr;
    static cudaEvent_t e0 = nullptr, eA = nullptr, eW = nullptr, e1 = nullptr, e2 = nullptr;
    if (sA == nullptr) {
        cudaStreamCreateWithFlags(&sA, cudaStreamNonBlocking);
        cudaStreamCreateWithFlags(&sB, cudaStreamNonBlocking);
        cudaEventCreateWithFlags(&e0, cudaEventDisableTiming);
        cudaEventCreateWithFlags(&eA, cudaEventDisableTiming);
        cudaEventCreateWithFlags(&eW, cudaEventDisableTiming);
        cudaEventCreateWithFlags(&e1, cudaEventDisableTiming);
        cudaEventCreateWithFlags(&e2, cudaEventDisableTiming);
        cudaFuncSetAttribute(k_gemm<0>, cudaFuncAttributeMaxDynamicSharedMemorySize, SMEM_H);
        cudaFuncSetAttribute(k_gemm<1>, cudaFuncAttributeMaxDynamicSharedMemorySize, SMEM_H);
        cudaFuncSetAttribute(k_gemm<2>, cudaFuncAttributeMaxDynamicSharedMemorySize, SMEM_H);
        cudaFuncSetAttribute(k_outt, cudaFuncAttributeMaxDynamicSharedMemorySize, SMEM_OUT);
    }

    const size_t knoff = (size_t)L * B * HALF;
    const size_t groff = (size_t)16 * NBLK * GSZ;

    // fork: gather + remaining weight conversions on sA; w1 conversion on default
    cudaEventRecord(e0, 0);
    cudaStreamWaitEvent(sA, e0, 0);
    k_gather<<<TOK, 128, 0, sA>>>(seq, embed, h0h);
    cudaEventRecord(eA, sA);
    k_round_rest<<<768 + (int)(((size_t)V * H) / 1024), 256, 0, sA>>>(
        ff_w2, sem_w, epi_w, out_w, w2h, wch, owh);
    cudaEventRecord(eW, sA);

    k_round_w1<<<512, 256>>>(ff_w1, w1h);
    cudaStreamWaitEvent(0, eA, 0);
    k_gemm<1><<<dim3(2 * H / TN, TOK / TM), 256, SMEM_H>>>(h0h, w1h, ff_b1, ff1h, 2 * H, H);
    cudaStreamWaitEvent(0, eW, 0);
    k_gemm<0><<<dim3(H / TN, TOK / TM), 256, SMEM_H>>>(ff1h, w2h, ff_b2, y2h, H, 2 * H);
    k_ln<<<TOK / 8, 256>>>(y2h, h0h, gamma, beta, hh);

    // key projection, sem half -> fork gram+scan(m=0) onto sB
    k_gemm<2><<<dim3(HALF / TN, TOK / TM), 256, SMEM_H>>>(hh, wch, nullptr, kn, HALF, H);
    cudaEventRecord(e1, 0);
    cudaStreamWaitEvent(sB, e1, 0);
    k_gram<<<16 * NBLK, 32, 0, sB>>>(kn, gr);
    k_scan<<<16, 64, 0, sB>>>(kn, gr, c, 0);
    cudaEventRecord(e2, sB);

    // epi half + its gram/scan on default, concurrent with sB
    k_gemm<2><<<dim3(HALF / TN, TOK / TM), 256, SMEM_H>>>(hh, wch + (size_t)HALF * H,
                                                          nullptr, kn + knoff, HALF, H);
    k_gram<<<16 * NBLK, 32>>>(kn + knoff, gr + groff);
    k_scan<<<16, 64>>>(kn + knoff, gr + groff, c, HALF);

    // join and finish
    cudaStreamWaitEvent(0, e2, 0);
    k_rp<<<H / 16, 256>>>(c, rp_w, rp_b, r);
    k_outt<<<V / ONT, 128, SMEM_OUT>>>(r, owh, out_b, out);
}

// round 15
// speedup vs baseline: 1.0311x; 1.0311x over previous
#include <cuda_runtime.h>
#include <cuda_fp16.h>
#include <cstdint>

namespace {
constexpr int B = 16;
constexpr int L = 1024;
constexpr int H = 512;
constexpr int V = 32000;
constexpr int HALF = 256;
constexpr int TOK = B * L;           // 16384
constexpr float ALPHA_C = 0.05f;     // 1 - 0.95
constexpr float EPS_LN_C = 1e-5f;
constexpr float EPS_NORM_C = 1e-12f;

// GEMM tiling (fp16 operands, fp32 accum)
constexpr int TM = 128;
constexpr int TN = 128;
constexpr int TKH = 64;              // halves per k-tile = 128 bytes per row
constexpr int STG = 3;               // cp.async stages
constexpr int TILE_BYTES = 128 * 128;            // 16 KB per matrix per stage
constexpr int SMEM_H = STG * 2 * TILE_BYTES;     // 96 KB

// scan blocking
constexpr int NBLK = 127;            // 127*8 + 7 remainder = 1023 steps
constexpr int GSZ = 36;              // 28 pair-grams + 8 inv-norms per block

// logits tensor kernel
constexpr int ONT = 256;             // v-columns per CTA
constexpr int RS_STRIDE = 520;       // padded r row stride (halves) -> conflict-free ldsm
constexpr int WT_OFF = 17408;        // W tiles start (1024-aligned, after 16640B r_s)
constexpr int WT_TILE = 256 * 128;   // 32 KB per stage
constexpr int SMEM_OUT = WT_OFF + 3 * WT_TILE;   // 115712 B
}

// ---------------- scratch (static device globals; no allocation) ----------------
__device__ __half g_h0h[TOK * H];            // embed gather output (fp16)
__device__ __half g_ff1h[TOK * 2 * H];       // FFN hidden (fp16)
__device__ __half g_y2h[TOK * H];            // FFN output (pre-LN, fp16)
__device__ __half g_hh[TOK * H];             // post-LN hidden (fp16)
__device__ float  g_kn[2 * L * B * HALF];    // RAW keys [m][l][b][i]
__device__ float  g_gram[32 * NBLK * GSZ];   // precomputed grams+inv-norms
__device__ float  g_c[B * H];                // context
__device__ float  g_r[B * H];                // readout projection
__device__ __half g_w1h[2 * H * H];          // fp16 ff_w1
__device__ __half g_w2h[2 * H * H];          // fp16 ff_w2
__device__ __half g_wch[2 * HALF * H];       // fp16 [sem_w ; epi_w]
__device__ __half g_owh[(size_t)V * H];      // fp16 out_w

// ---------------- helpers ----------------
__device__ __forceinline__ uint32_t smem_u32(const void* p) {
    return (uint32_t)__cvta_generic_to_shared(p);
}
__device__ __forceinline__ void cp16(uint32_t dst, const void* src) {
    asm volatile("cp.async.cg.shared.global [%0], [%1], 16;" :: "r"(dst), "l"(src));
}
__device__ __forceinline__ uint32_t sw128(uint32_t off) {
    return off ^ ((off >> 3) & 0x70u);
}
__device__ __forceinline__ void ldsm_x4(uint32_t& r0, uint32_t& r1, uint32_t& r2,
                                        uint32_t& r3, uint32_t a) {
    asm volatile("ldmatrix.sync.aligned.m8n8.x4.shared.b16 {%0,%1,%2,%3}, [%4];"
                 : "=r"(r0), "=r"(r1), "=r"(r2), "=r"(r3) : "r"(a));
}
__device__ __forceinline__ void ldsm_x2(uint32_t& r0, uint32_t& r1, uint32_t a) {
    asm volatile("ldmatrix.sync.aligned.m8n8.x2.shared.b16 {%0,%1}, [%2];"
                 : "=r"(r0), "=r"(r1) : "r"(a));
}
__device__ __forceinline__ void mma_f16(float* d, const uint32_t* a, const uint32_t* b) {
    asm volatile(
        "mma.sync.aligned.m16n8k16.row.col.f32.f16.f16.f32 "
        "{%0,%1,%2,%3},{%4,%5,%6,%7},{%8,%9},{%0,%1,%2,%3};"
        : "+f"(d[0]), "+f"(d[1]), "+f"(d[2]), "+f"(d[3])
        : "r"(a[0]), "r"(a[1]), "r"(a[2]), "r"(a[3]), "r"(b[0]), "r"(b[1]));
}

// ---------------- weight conversions ----------------
__global__ void k_round_w1(const float* __restrict__ w1, __half* __restrict__ d1) {
    int i = blockIdx.x * 256 + threadIdx.x;
    float4 v = __ldg(reinterpret_cast<const float4*>(w1) + i);
    __half2* d = reinterpret_cast<__half2*>(d1) + i * 2;
    d[0] = __floats2half2_rn(v.x, v.y);
    d[1] = __floats2half2_rn(v.z, v.w);
}

// blocks [0,512): ff_w2 ; [512,640): sem ; [640,768): epi ; [768,16768): out_w
__global__ void k_round_rest(const float* __restrict__ w2,
                             const float* __restrict__ sem, const float* __restrict__ epi,
                             const float* __restrict__ ow,
                             __half* __restrict__ d2, __half* __restrict__ dc,
                             __half* __restrict__ dow) {
    int blk = blockIdx.x;
    const float* src;
    __half* dst;
    int base;
    if (blk < 512)      { src = w2;  dst = d2; base = blk; }
    else if (blk < 640) { src = sem; dst = dc; base = blk - 512; }
    else if (blk < 768) { src = epi; dst = dc + (size_t)HALF * H; base = blk - 640; }
    else                { src = ow;  dst = dow; base = blk - 768; }
    size_t i = (size_t)base * 256 + threadIdx.x;
    float4 v = __ldg(reinterpret_cast<const float4*>(src) + i);
    __half2* d = reinterpret_cast<__half2*>(dst) + i * 2;
    d[0] = __floats2half2_rn(v.x, v.y);
    d[1] = __floats2half2_rn(v.z, v.w);
}

// ---------------- embedding gather (fp16 out) ----------------
__global__ void k_gather(const int* __restrict__ seq, const float* __restrict__ embed,
                         __half* __restrict__ out) {
    int t = blockIdx.x;
    int v = seq[t];
    const float4* src = reinterpret_cast<const float4*>(embed + (size_t)v * H);
    float4 x = src[threadIdx.x];
    __half2* dst = reinterpret_cast<__half2*>(out + (size_t)t * H) + threadIdx.x * 2;
    dst[0] = __floats2half2_rn(x.x, x.y);
    dst[1] = __floats2half2_rn(x.z, x.w);
}

// ---------------- fp16 tensor GEMM ----------------
// MODE 0: +bias -> fp16; MODE 1: +bias+relu -> fp16; MODE 2: raw fp32 scatter [l][b][c]
template <int MODE>
__global__ void __launch_bounds__(256) k_gemm(const __half* __restrict__ A,
                                              const __half* __restrict__ W,
                                              const float* __restrict__ bias,
                                              void* __restrict__ Cv,
                                              int N, int K) {
    extern __shared__ char smem[];
    const uint32_t sb = smem_u32(smem);
    uint32_t a_off[STG], w_off[STG];
#pragma unroll
    for (int s = 0; s < STG; ++s) {
        a_off[s] = s * 2 * TILE_BYTES;
        w_off[s] = s * 2 * TILE_BYTES + TILE_BYTES;
    }

    const int tid = threadIdx.x;
    const int bm = blockIdx.y * TM;
    const int bn = blockIdx.x * TN;
    const int warp = tid >> 5, lane = tid & 31;
    const int wm = warp >> 2, wn = warp & 3;
    const int g = lane >> 2, tg = lane & 3;

    const int row = tid >> 1;
    const int h64 = tid & 1;
    const __half* Ag = A + (size_t)(bm + row) * K + h64 * 32;
    const __half* Wg = W + (size_t)(bn + row) * K + h64 * 32;
    uint32_t swz[4];
#pragma unroll
    for (int c = 0; c < 4; ++c) swz[c] = sw128(row * 128 + h64 * 64 + c * 16);

    float acc[4][4][4];
#pragma unroll
    for (int mi = 0; mi < 4; ++mi)
#pragma unroll
        for (int ni = 0; ni < 4; ++ni)
#pragma unroll
            for (int q = 0; q < 4; ++q) acc[mi][ni][q] = 0.f;

    auto issue_tile = [&](int st, int kt) {
#pragma unroll
        for (int c = 0; c < 4; ++c)
            cp16(sb + a_off[st] + swz[c], Ag + (size_t)kt * TKH + c * 8);
#pragma unroll
        for (int c = 0; c < 4; ++c)
            cp16(sb + w_off[st] + swz[c], Wg + (size_t)kt * TKH + c * 8);
        asm volatile("cp.async.commit_group;" ::: "memory");
    };

    const int a_r = lane & 15;
    const int a_cb = (lane >> 4) * 16;
    const int b_r = lane & 7;
    const int b_cb = ((lane >> 3) & 1) * 16;

    auto mma_pass = [&](int buf) {
#pragma unroll
        for (int ak = 0; ak < 4; ++ak) {
            const int kb = ak * 32;
            uint32_t afrag[4][4];
#pragma unroll
            for (int mi = 0; mi < 4; ++mi) {
                uint32_t addr = sb + a_off[buf] +
                    sw128((uint32_t)(wm * 64 + mi * 16 + a_r) * 128 + kb + a_cb);
                ldsm_x4(afrag[mi][0], afrag[mi][1], afrag[mi][2], afrag[mi][3], addr);
            }
            uint32_t bfrag[4][2];
#pragma unroll
            for (int ni = 0; ni < 4; ++ni) {
                uint32_t addr = sb + w_off[buf] +
                    sw128((uint32_t)(wn * 32 + ni * 8 + b_r) * 128 + kb + b_cb);
                ldsm_x2(bfrag[ni][0], bfrag[ni][1], addr);
            }
#pragma unroll
            for (int mi = 0; mi < 4; ++mi)
#pragma unroll
                for (int ni = 0; ni < 4; ++ni)
                    mma_f16(acc[mi][ni], afrag[mi], bfrag[ni]);
        }
    };

    const int NPASS = K / TKH;
    issue_tile(0, 0);
    issue_tile(1, 1);

    int p = 0;
    for (; p < NPASS - 1; ++p) {
        asm volatile("cp.async.wait_group 1;" ::: "memory");
        __syncthreads();
        if (p + 2 < NPASS) issue_tile((p + 2) % STG, p + 2);
        mma_pass(p % STG);
    }
    asm volatile("cp.async.wait_group 0;" ::: "memory");
    __syncthreads();
    mma_pass(p % STG);

#pragma unroll
    for (int mi = 0; mi < 4; ++mi) {
#pragma unroll
        for (int half = 0; half < 2; ++half) {
            int r = bm + wm * 64 + mi * 16 + g + half * 8;
#pragma unroll
            for (int ni = 0; ni < 4; ++ni) {
                int col = bn + wn * 32 + ni * 8 + tg * 2;
                float x = acc[mi][ni][half * 2 + 0];
                float y = acc[mi][ni][half * 2 + 1];
                if (MODE == 2) {
                    int b_ = r >> 10, l_ = r & 1023;
                    float* dst = (float*)Cv + ((size_t)l_ * B + b_) * HALF + col;
                    *reinterpret_cast<float2*>(dst) = make_float2(x, y);
                } else {
                    x += bias[col];
                    y += bias[col + 1];
                    if (MODE == 1) { x = fmaxf(x, 0.f); y = fmaxf(y, 0.f); }
                    __half* dst = (__half*)Cv + (size_t)r * N + col;
                    *reinterpret_cast<__half2*>(dst) = __floats2half2_rn(x, y);
                }
            }
        }
    }
}

// ---------------- residual + LayerNorm (warp per row; fp16 in/out) ----------------
__global__ void k_ln(const __half* __restrict__ y2, const __half* __restrict__ h0,
                     const float* __restrict__ gamma, const float* __restrict__ beta,
                     __half* __restrict__ out) {
    int warp = threadIdx.x >> 5, lane = threadIdx.x & 31;
    int row = blockIdx.x * 8 + warp;
    const __half2* a = reinterpret_cast<const __half2*>(y2 + (size_t)row * H);
    const __half2* hb = reinterpret_cast<const __half2*>(h0 + (size_t)row * H);
    float x[16];
    float s = 0.f, s2 = 0.f;
#pragma unroll
    for (int i = 0; i < 4; ++i) {
        int idx = (lane + i * 32) * 2;
        float2 u0 = __half22float2(a[idx]);
        float2 u1 = __half22float2(a[idx + 1]);
        float2 v0 = __half22float2(hb[idx]);
        float2 v1 = __half22float2(hb[idx + 1]);
        float t0 = u0.x + v0.x, t1 = u0.y + v0.y, t2 = u1.x + v1.x, t3 = u1.y + v1.y;
        x[i * 4 + 0] = t0; x[i * 4 + 1] = t1; x[i * 4 + 2] = t2; x[i * 4 + 3] = t3;
        s += t0 + t1 + t2 + t3;
        s2 += t0 * t0 + t1 * t1 + t2 * t2 + t3 * t3;
    }
#pragma unroll
    for (int off = 16; off > 0; off >>= 1) {
        s += __shfl_xor_sync(0xffffffffu, s, off);
        s2 += __shfl_xor_sync(0xffffffffu, s2, off);
    }
    float mu = s * (1.f / H);
    float var = s2 * (1.f / H) - mu * mu;
    float rstd = rsqrtf(var + EPS_LN_C);
    __half2* o = reinterpret_cast<__half2*>(out + (size_t)row * H);
    const float4* g4 = reinterpret_cast<const float4*>(gamma);
    const float4* b4 = reinterpret_cast<const float4*>(beta);
#pragma unroll
    for (int i = 0; i < 4; ++i) {
        float4 gg = __ldg(g4 + lane + i * 32);
        float4 bb = __ldg(b4 + lane + i * 32);
        float r0 = (x[i * 4 + 0] - mu) * rstd * gg.x + bb.x;
        float r1 = (x[i * 4 + 1] - mu) * rstd * gg.y + bb.y;
        float r2 = (x[i * 4 + 2] - mu) * rstd * gg.z + bb.z;
        float r3 = (x[i * 4 + 3] - mu) * rstd * gg.w + bb.w;
        o[(lane + i * 32) * 2] = __floats2half2_rn(r0, r1);
        o[(lane + i * 32) * 2 + 1] = __floats2half2_rn(r2, r3);
    }
}

// ---------------- Gram precompute (per m-half): one warp per (b,kblk) --------
__global__ void __launch_bounds__(32) k_gram(const float* __restrict__ kn_m,
                                             float* __restrict__ gram_m) {
    const int bx = blockIdx.x;
    const int b = bx / NBLK;
    const int kblk = bx - b * NBLK;
    const int lane = threadIdx.x;
    const float* kn = kn_m + b * HALF;
    const int t0 = 7 + 8 * kblk;
    const int STRD = B * HALF;

    float k8[8][8];
#pragma unroll
    for (int j = 0; j < 8; ++j) {
        const float4* p = reinterpret_cast<const float4*>(
            kn + (size_t)(t0 + j) * STRD + lane * 8);
        float4 u = __ldg(p), w = __ldg(p + 1);
        k8[j][0] = u.x; k8[j][1] = u.y; k8[j][2] = u.z; k8[j][3] = u.w;
        k8[j][4] = w.x; k8[j][5] = w.y; k8[j][6] = w.z; k8[j][7] = w.w;
    }
    float red[GSZ];
#pragma unroll
    for (int q = 0; q < GSZ; ++q) red[q] = 0.f;
#pragma unroll
    for (int e = 0; e < 8; ++e) {
        int p = 0;
#pragma unroll
        for (int j = 0; j < 8; ++j) {
#pragma unroll
            for (int i = j + 1; i < 8; ++i) {
                red[p] += k8[j][e] * k8[i][e];
                ++p;
            }
        }
#pragma unroll
        for (int j = 0; j < 8; ++j) red[28 + j] += k8[j][e] * k8[j][e];
    }
#pragma unroll
    for (int off = 16; off > 0; off >>= 1)
#pragma unroll
        for (int q = 0; q < GSZ; ++q)
            red[q] += __shfl_xor_sync(0xffffffffu, red[q], off);

    if (lane == 0) {
        float iv[8];
#pragma unroll
        for (int j = 0; j < 8; ++j)
            iv[j] = 1.f / fmaxf(sqrtf(red[28 + j]), EPS_NORM_C);
        float o[GSZ];
        int p = 0;
#pragma unroll
        for (int j = 0; j < 8; ++j)
#pragma unroll
            for (int i = j + 1; i < 8; ++i) {
                o[p] = ALPHA_C * red[p] * iv[j] * iv[i];
                ++p;
            }
#pragma unroll
        for (int j = 0; j < 8; ++j) o[28 + j] = iv[j];
        float4* dst = reinterpret_cast<float4*>(gram_m + (size_t)bx * GSZ);
#pragma unroll
        for (int q = 0; q < 9; ++q)
            dst[q] = make_float4(o[q * 4], o[q * 4 + 1], o[q * 4 + 2], o[q * 4 + 3]);
    }
}

// ---------------- EMA scan (per m-half): 8-step blocks, smem ring (1 warp) ----
#define GP(j, i) gb[(j) * 7 - (j) * ((j) - 1) / 2 + (i) - (j) - 1]

__global__ void __launch_bounds__(32) k_scan(const float* __restrict__ kn_m,
                                             const float* __restrict__ gram_m,
                                             float* __restrict__ cbuf, int moff) {
    const int lane = threadIdx.x;
    const int b = blockIdx.x;
    const float* kn = kn_m + b * HALF;
    const int STRD = B * HALF;

    __shared__ float stg[3][2048 + 64];

    auto prefetch = [&](int st, int kblk) {
        int t0 = 7 + 8 * kblk;
#pragma unroll
        for (int j = 0; j < 8; ++j) {
            const float* src = kn + (size_t)(t0 + j) * STRD + lane * 8;
            uint32_t dst = smem_u32(&stg[st][j * 256 + lane * 8]);
            cp16(dst, src);
            cp16(dst + 16, src + 4);
        }
        if (lane < 9)
            cp16(smem_u32(&stg[st][2048 + lane * 4]),
                 gram_m + (size_t)(b * NBLK + kblk) * GSZ + lane * 4);
        asm volatile("cp.async.commit_group;" ::: "memory");
    };

    float v[8], cac[8];
    {
        const float4* p = reinterpret_cast<const float4*>(
            kn + (size_t)(L - 1) * STRD + lane * 8);
        float4 u = __ldg(p), w = __ldg(p + 1);
        v[0] = u.x; v[1] = u.y; v[2] = u.z; v[3] = u.w;
        v[4] = w.x; v[5] = w.y; v[6] = w.z; v[7] = w.w;
    }
#pragma unroll
    for (int j = 0; j < 8; ++j) cac[j] = 0.f;

    prefetch(0, NBLK - 1);
    prefetch(1, NBLK - 2);
    prefetch(2, NBLK - 3);

    for (int it = 0; it < NBLK; ++it) {
        int st = it % 3;
        asm volatile("cp.async.wait_group 2;" ::: "memory");
        __syncwarp();
        float cur[8][8];
#pragma unroll
        for (int j = 0; j < 8; ++j) {
            float4 u = *reinterpret_cast<const float4*>(&stg[st][j * 256 + lane * 8]);
            float4 w = *reinterpret_cast<const float4*>(&stg[st][j * 256 + lane * 8 + 4]);
            cur[j][0] = u.x; cur[j][1] = u.y; cur[j][2] = u.z; cur[j][3] = u.w;
            cur[j][4] = w.x; cur[j][5] = w.y; cur[j][6] = w.z; cur[j][7] = w.w;
        }
        float gb[GSZ];
#pragma unroll
        for (int q = 0; q < 9; ++q) {
            float4 t = *reinterpret_cast<const float4*>(&stg[st][2048 + q * 4]);
            gb[q * 4] = t.x; gb[q * 4 + 1] = t.y; gb[q * 4 + 2] = t.z; gb[q * 4 + 3] = t.w;
        }
        __syncwarp();
        if (it + 3 < NBLK) prefetch(st, NBLK - 1 - (it + 3));

        float u[8];
#pragma unroll
        for (int j = 0; j < 8; ++j) {
            float d = cur[j][0] * v[0];
#pragma unroll
            for (int e = 1; e < 8; ++e) d += cur[j][e] * v[e];
            u[j] = d;
        }
#pragma unroll
        for (int off = 16; off > 0; off >>= 1)
#pragma unroll
            for (int j = 0; j < 8; ++j)
                u[j] += __shfl_xor_sync(0xffffffffu, u[j], off);

        float s7 = gb[35] * u[7];
        float s6 = gb[34] * u[6] - GP(6, 7) * s7;
        float s5 = gb[33] * u[5] - GP(5, 7) * s7 - GP(5, 6) * s6;
        float s4 = gb[32] * u[4] - GP(4, 7) * s7 - GP(4, 6) * s6 - GP(4, 5) * s5;
        float s3 = gb[31] * u[3] - GP(3, 7) * s7 - GP(3, 6) * s6 - GP(3, 5) * s5
                 - GP(3, 4) * s4;
        float s2 = gb[30] * u[2] - GP(2, 7) * s7 - GP(2, 6) * s6 - GP(2, 5) * s5
                 - GP(2, 4) * s4 - GP(2, 3) * s3;
        float s1 = gb[29] * u[1] - GP(1, 7) * s7 - GP(1, 6) * s6 - GP(1, 5) * s5
                 - GP(1, 4) * s4 - GP(1, 3) * s3 - GP(1, 2) * s2;
        float s0 = gb[28] * u[0] - GP(0, 7) * s7 - GP(0, 6) * s6 - GP(0, 5) * s5
                 - GP(0, 4) * s4 - GP(0, 3) * s3 - GP(0, 2) * s2 - GP(0, 1) * s1;

        float a0 = ALPHA_C * gb[28] * s0, a1 = ALPHA_C * gb[29] * s1;
        float a2 = ALPHA_C * gb[30] * s2, a3 = ALPHA_C * gb[31] * s3;
        float a4 = ALPHA_C * gb[32] * s4, a5 = ALPHA_C * gb[33] * s5;
        float a6 = ALPHA_C * gb[34] * s6, a7 = ALPHA_C * gb[35] * s7;

#pragma unroll
        for (int e = 0; e < 8; ++e) {
            float dv = cur[0][e] * a0 + cur[1][e] * a1 + cur[2][e] * a2 + cur[3][e] * a3
                     + cur[4][e] * a4 + cur[5][e] * a5 + cur[6][e] * a6 + cur[7][e] * a7;
            float dc = cur[0][e] * s0 + cur[1][e] * s1 + cur[2][e] * s2 + cur[3][e] * s3
                     + cur[4][e] * s4 + cur[5][e] * s5 + cur[6][e] * s6 + cur[7][e] * s7;
            v[e] -= dv;
            cac[e] += dc;
        }
    }

    for (int t = 6; t >= 0; --t) {
        float kt[8];
        const float4* p = reinterpret_cast<const float4*>(kn + (size_t)t * STRD + lane * 8);
        float4 u = __ldg(p), w = __ldg(p + 1);
        kt[0] = u.x; kt[1] = u.y; kt[2] = u.z; kt[3] = u.w;
        kt[4] = w.x; kt[5] = w.y; kt[6] = w.z; kt[7] = w.w;
        float du = 0.f, dg = 0.f;
#pragma unroll
        for (int j = 0; j < 8; ++j) { du += kt[j] * v[j]; dg += kt[j] * kt[j]; }
#pragma unroll
        for (int off = 16; off > 0; off >>= 1) {
            du += __shfl_xor_sync(0xffffffffu, du, off);
            dg += __shfl_xor_sync(0xffffffffu, dg, off);
        }
        float inv = 1.f / fmaxf(sqrtf(dg), EPS_NORM_C);
        float s = du * inv;
        float av = ALPHA_C * inv * s;
#pragma unroll
        for (int j = 0; j < 8; ++j) {
            cac[j] += kt[j] * s;
            v[j] -= kt[j] * av;
        }
    }

    float* out = cbuf + b * H + moff + lane * 8;
#pragma unroll
    for (int j = 0; j < 8; ++j) out[j] = ALPHA_C * cac[j];
}

// ---------------- r = c @ rp_w^T + rp_b ----------------
__global__ void k_rp(const float* __restrict__ c, const float* __restrict__ W,
                     const float* __restrict__ bias, float* __restrict__ r) {
    __shared__ float cs[B * (H + 1)];
    for (int i = threadIdx.x; i < B * H; i += 256) {
        int bb = i >> 9, hh = i & 511;
        cs[bb * (H + 1) + hh] = c[i];
    }
    __syncthreads();
    int g = blockIdx.x * 16 + (threadIdx.x >> 4);
    int b = threadIdx.x & 15;
    const float* w = W + (size_t)g * H;
    const float* cb = &cs[b * (H + 1)];
    float acc = 0.f;
    for (int h = 0; h < H; h += 4) {
        float4 wv = __ldg(reinterpret_cast<const float4*>(w + h));
        acc += cb[h] * wv.x + cb[h + 1] * wv.y + cb[h + 2] * wv.z + cb[h + 3] * wv.w;
    }
    r[b * H + g] = acc + bias[g];
}

// ---------------- logits via tensor cores ----------------
__global__ void __launch_bounds__(128) k_outt(const float* __restrict__ r,
                                              const __half* __restrict__ Wh,
                                              const float* __restrict__ bias,
                                              float* __restrict__ out) {
    extern __shared__ char smem[];
    __half* r_s = reinterpret_cast<__half*>(smem);
    const uint32_t sb = smem_u32(smem);
    const int tid = threadIdx.x;
    const int warp = tid >> 5, lane = tid & 31;
    const int bn = blockIdx.x * ONT;
    const int g = lane >> 2, tg = lane & 3;

#pragma unroll
    for (int j = 0; j < 16; ++j) {
        int f = tid + j * 128;
        float4 v = __ldg(reinterpret_cast<const float4*>(r) + f);
        int row = (f * 4) >> 9, col = (f * 4) & 511;
        __half2* d = reinterpret_cast<__half2*>(r_s + row * RS_STRIDE + col);
        d[0] = __floats2half2_rn(v.x, v.y);
        d[1] = __floats2half2_rn(v.z, v.w);
    }

    auto wtile = [&](int st, int kt) {
#pragma unroll
        for (int rr = 0; rr < 2; ++rr) {
            int row = rr * 128 + tid;
            const __half* s = Wh + (size_t)(bn + row) * H + kt * TKH;
            uint32_t base = sb + WT_OFF + st * WT_TILE;
#pragma unroll
            for (int c = 0; c < 8; ++c)
                cp16(base + sw128((uint32_t)row * 128 + c * 16), s + c * 8);
        }
        asm volatile("cp.async.commit_group;" ::: "memory");
    };

    float acc[8][4];
#pragma unroll
    for (int ni = 0; ni < 8; ++ni)
#pragma unroll
        for (int q = 0; q < 4; ++q) acc[ni][q] = 0.f;

    auto opass = [&](int buf, int kt) {
#pragma unroll
        for (int ak = 0; ak < 4; ++ak) {
            uint32_t af[4];
            uint32_t aaddr = sb + (uint32_t)((lane & 15) * RS_STRIDE * 2 +
                                             kt * 128 + ak * 32 + (lane >> 4) * 16);
            ldsm_x4(af[0], af[1], af[2], af[3], aaddr);
            uint32_t bf[8][2];
#pragma unroll
            for (int ni = 0; ni < 8; ++ni) {
                uint32_t addr = sb + WT_OFF + buf * WT_TILE +
                    sw128((uint32_t)(warp * 64 + ni * 8 + (lane & 7)) * 128 + ak * 32 +
                          ((lane >> 3) & 1) * 16);
                ldsm_x2(bf[ni][0], bf[ni][1], addr);
            }
#pragma unroll
            for (int ni = 0; ni < 8; ++ni)
                mma_f16(acc[ni], af, bf[ni]);
        }
    };

    const int NP = H / TKH;   // 8
    wtile(0, 0);
    wtile(1, 1);
    int p = 0;
    for (; p < NP - 1; ++p) {
        asm volatile("cp.async.wait_group 1;" ::: "memory");
        __syncthreads();
        if (p + 2 < NP) wtile((p + 2) % 3, p + 2);
        opass(p % 3, p);
    }
    asm volatile("cp.async.wait_group 0;" ::: "memory");
    __syncthreads();
    opass(p % 3, p);

#pragma unroll
    for (int ni = 0; ni < 8; ++ni) {
        int col = bn + warp * 64 + ni * 8 + tg * 2;
        float bx = __ldg(bias + col);
        float by = __ldg(bias + col + 1);
#pragma unroll
        for (int half = 0; half < 2; ++half) {
            int b = g + half * 8;
            float x = acc[ni][half * 2 + 0] + bx;
            float y = acc[ni][half * 2 + 1] + by;
            *reinterpret_cast<float2*>(out + (size_t)b * V + col) = make_float2(x, y);
        }
    }
}

// ---------------- launch (forked-stream graph; resources created once) -------
extern "C" void kernel_launch(void* const* d_in, const int* in_sizes, int n_in,
                              void* d_out, int out_size) {
    const int*   seq   = (const int*)d_in[0];
    const float* embed = (const float*)d_in[1];
    const float* ff_w1 = (const float*)d_in[2];
    const float* ff_b1 = (const float*)d_in[3];
    const float* ff_w2 = (const float*)d_in[4];
    const float* ff_b2 = (const float*)d_in[5];
    const float* gamma = (const float*)d_in[6];
    const float* beta  = (const float*)d_in[7];
    const float* sem_w = (const float*)d_in[8];
    const float* epi_w = (const float*)d_in[9];
    const float* rp_w  = (const float*)d_in[10];
    const float* rp_b  = (const float*)d_in[11];
    const float* out_w = (const float*)d_in[12];
    const float* out_b = (const float*)d_in[13];
    float* out = (float*)d_out;

    __half *h0h, *ff1h, *y2h, *hh, *w1h, *w2h, *wch, *owh;
    float *kn, *gr, *c, *r;
    cudaGetSymbolAddress((void**)&h0h,  g_h0h);
    cudaGetSymbolAddress((void**)&ff1h, g_ff1h);
    cudaGetSymbolAddress((void**)&y2h,  g_y2h);
    cudaGetSymbolAddress((void**)&hh,   g_hh);
    cudaGetSymbolAddress((void**)&kn,   g_kn);
    cudaGetSymbolAddress((void**)&gr,   g_gram);
    cudaGetSymbolAddress((void**)&c,    g_c);
    cudaGetSymbolAddress((void**)&r,    g_r);
    cudaGetSymbolAddress((void**)&w1h,  g_w1h);
    cudaGetSymbolAddress((void**)&w2h,  g_w2h);
    cudaGetSymbolAddress((void**)&wch,  g_wch);
    cudaGetSymbolAddress((void**)&owh,  g_owh);

    static cudaStream_t sA = nullptr, sB = nullptr;
    static cudaEvent_t e0 = nullptr, eA = nullptr, eW = nullptr, eL = nullptr, e2 = nullptr;
    if (sA == nullptr) {
        cudaStreamCreateWithFlags(&sA, cudaStreamNonBlocking);
        cudaStreamCreateWithFlags(&sB, cudaStreamNonBlocking);
        cudaEventCreateWithFlags(&e0, cudaEventDisableTiming);
        cudaEventCreateWithFlags(&eA, cudaEventDisableTiming);
        cudaEventCreateWithFlags(&eW, cudaEventDisableTiming);
        cudaEventCreateWithFlags(&eL, cudaEventDisableTiming);
        cudaEventCreateWithFlags(&e2, cudaEventDisableTiming);
        cudaFuncSetAttribute(k_gemm<0>, cudaFuncAttributeMaxDynamicSharedMemorySize, SMEM_H);
        cudaFuncSetAttribute(k_gemm<1>, cudaFuncAttributeMaxDynamicSharedMemorySize, SMEM_H);
        cudaFuncSetAttribute(k_gemm<2>, cudaFuncAttributeMaxDynamicSharedMemorySize, SMEM_H);
        cudaFuncSetAttribute(k_outt, cudaFuncAttributeMaxDynamicSharedMemorySize, SMEM_OUT);
    }

    const size_t knoff = (size_t)L * B * HALF;
    const size_t groff = (size_t)16 * NBLK * GSZ;

    // fork: gather + remaining weight conversions on sA; w1 conversion on default
    cudaEventRecord(e0, 0);
    cudaStreamWaitEvent(sA, e0, 0);
    k_gather<<<TOK, 128, 0, sA>>>(seq, embed, h0h);
    cudaEventRecord(eA, sA);
    k_round_rest<<<768 + (int)(((size_t)V * H) / 1024), 256, 0, sA>>>(
        ff_w2, sem_w, epi_w, out_w, w2h, wch, owh);
    cudaEventRecord(eW, sA);

    k_round_w1<<<512, 256>>>(ff_w1, w1h);
    cudaStreamWaitEvent(0, eA, 0);
    k_gemm<1><<<dim3(2 * H / TN, TOK / TM), 256, SMEM_H>>>(h0h, w1h, ff_b1, ff1h, 2 * H, H);
    cudaStreamWaitEvent(0, eW, 0);
    k_gemm<0><<<dim3(H / TN, TOK / TM), 256, SMEM_H>>>(ff1h, w2h, ff_b2, y2h, H, 2 * H);
    k_ln<<<TOK / 8, 256>>>(y2h, h0h, gamma, beta, hh);
    cudaEventRecord(eL, 0);

    // fork after LN: sem chain on sB, epi chain on default, fully concurrent
    cudaStreamWaitEvent(sB, eL, 0);
    k_gemm<2><<<dim3(HALF / TN, TOK / TM), 256, SMEM_H, sB>>>(hh, wch, nullptr, kn, HALF, H);
    k_gram<<<16 * NBLK, 32, 0, sB>>>(kn, gr);
    k_scan<<<16, 32, 0, sB>>>(kn, gr, c, 0);
    cudaEventRecord(e2, sB);

    k_gemm<2><<<dim3(HALF / TN, TOK / TM), 256, SMEM_H>>>(hh, wch + (size_t)HALF * H,
                                                          nullptr, kn + knoff, HALF, H);
    k_gram<<<16 * NBLK, 32>>>(kn + knoff, gr + groff);
    k_scan<<<16, 32>>>(kn + knoff, gr + groff, c, HALF);

    // join and finish
    cudaStreamWaitEvent(0, e2, 0);
    k_rp<<<H / 16, 256>>>(c, rp_w, rp_b, r);
    k_outt<<<V / ONT, 128, SMEM_OUT>>>(r, owh, out_b, out);
}

// round 16
// speedup vs baseline: 1.0312x; 1.0001x over previous
#include <cuda_runtime.h>
#include <cuda_fp16.h>
#include <cstdint>

namespace {
constexpr int B = 16;
constexpr int L = 1024;
constexpr int H = 512;
constexpr int V = 32000;
constexpr int HALF = 256;
constexpr int TOK = B * L;           // 16384
constexpr int TOKH = TOK / 2;        // 8192 (token half)
constexpr float ALPHA_C = 0.05f;     // 1 - 0.95
constexpr float EPS_LN_C = 1e-5f;
constexpr float EPS_NORM_C = 1e-12f;

// GEMM tiling (fp16 operands, fp32 accum)
constexpr int TM = 128;
constexpr int TN = 128;
constexpr int TKH = 64;              // halves per k-tile = 128 bytes per row
constexpr int STG = 3;               // cp.async stages
constexpr int TILE_BYTES = 128 * 128;            // 16 KB per matrix per stage
constexpr int SMEM_H = STG * 2 * TILE_BYTES;     // 96 KB

// scan blocking
constexpr int NBLK = 127;            // 127*8 + 7 remainder = 1023 steps
constexpr int GSZ = 36;              // 28 pair-grams + 8 inv-norms per block

// logits tensor kernel
constexpr int ONT = 256;             // v-columns per CTA
constexpr int RS_STRIDE = 520;       // padded r row stride (halves) -> conflict-free ldsm
constexpr int WT_OFF = 17408;        // W tiles start (1024-aligned, after 16640B r_s)
constexpr int WT_TILE = 256 * 128;   // 32 KB per stage
constexpr int SMEM_OUT = WT_OFF + 3 * WT_TILE;   // 115712 B
}

// ---------------- scratch (static device globals; no allocation) ----------------
__device__ __half g_h0h[TOK * H];            // embed gather output (fp16)
__device__ __half g_ff1h[TOK * 2 * H];       // FFN hidden (fp16)
__device__ __half g_y2h[TOK * H];            // FFN output (pre-LN, fp16)
__device__ __half g_hh[TOK * H];             // post-LN hidden (fp16)
__device__ float  g_kn[2 * L * B * HALF];    // RAW keys [m][l][b][i]
__device__ float  g_gram[32 * NBLK * GSZ];   // precomputed grams+inv-norms
__device__ float  g_c[B * H];                // context
__device__ float  g_r[B * H];                // readout projection
__device__ __half g_w1h[2 * H * H];          // fp16 ff_w1
__device__ __half g_w2h[2 * H * H];          // fp16 ff_w2
__device__ __half g_wch[2 * HALF * H];       // fp16 [sem_w ; epi_w]
__device__ __half g_owh[(size_t)V * H];      // fp16 out_w

// ---------------- helpers ----------------
__device__ __forceinline__ uint32_t smem_u32(const void* p) {
    return (uint32_t)__cvta_generic_to_shared(p);
}
__device__ __forceinline__ void cp16(uint32_t dst, const void* src) {
    asm volatile("cp.async.cg.shared.global [%0], [%1], 16;" :: "r"(dst), "l"(src));
}
__device__ __forceinline__ uint32_t sw128(uint32_t off) {
    return off ^ ((off >> 3) & 0x70u);
}
__device__ __forceinline__ void ldsm_x4(uint32_t& r0, uint32_t& r1, uint32_t& r2,
                                        uint32_t& r3, uint32_t a) {
    asm volatile("ldmatrix.sync.aligned.m8n8.x4.shared.b16 {%0,%1,%2,%3}, [%4];"
                 : "=r"(r0), "=r"(r1), "=r"(r2), "=r"(r3) : "r"(a));
}
__device__ __forceinline__ void ldsm_x2(uint32_t& r0, uint32_t& r1, uint32_t a) {
    asm volatile("ldmatrix.sync.aligned.m8n8.x2.shared.b16 {%0,%1}, [%2];"
                 : "=r"(r0), "=r"(r1) : "r"(a));
}
__device__ __forceinline__ void mma_f16(float* d, const uint32_t* a, const uint32_t* b) {
    asm volatile(
        "mma.sync.aligned.m16n8k16.row.col.f32.f16.f16.f32 "
        "{%0,%1,%2,%3},{%4,%5,%6,%7},{%8,%9},{%0,%1,%2,%3};"
        : "+f"(d[0]), "+f"(d[1]), "+f"(d[2]), "+f"(d[3])
        : "r"(a[0]), "r"(a[1]), "r"(a[2]), "r"(a[3]), "r"(b[0]), "r"(b[1]));
}

// ---------------- weight conversions ----------------
__global__ void k_round_w1(const float* __restrict__ w1, __half* __restrict__ d1) {
    int i = blockIdx.x * 256 + threadIdx.x;
    float4 v = __ldg(reinterpret_cast<const float4*>(w1) + i);
    __half2* d = reinterpret_cast<__half2*>(d1) + i * 2;
    d[0] = __floats2half2_rn(v.x, v.y);
    d[1] = __floats2half2_rn(v.z, v.w);
}

// blocks [0,512): ff_w2 ; [512,640): sem ; [640,768): epi ; [768,16768): out_w
__global__ void k_round_rest(const float* __restrict__ w2,
                             const float* __restrict__ sem, const float* __restrict__ epi,
                             const float* __restrict__ ow,
                             __half* __restrict__ d2, __half* __restrict__ dc,
                             __half* __restrict__ dow) {
    int blk = blockIdx.x;
    const float* src;
    __half* dst;
    int base;
    if (blk < 512)      { src = w2;  dst = d2; base = blk; }
    else if (blk < 640) { src = sem; dst = dc; base = blk - 512; }
    else if (blk < 768) { src = epi; dst = dc + (size_t)HALF * H; base = blk - 640; }
    else                { src = ow;  dst = dow; base = blk - 768; }
    size_t i = (size_t)base * 256 + threadIdx.x;
    float4 v = __ldg(reinterpret_cast<const float4*>(src) + i);
    __half2* d = reinterpret_cast<__half2*>(dst) + i * 2;
    d[0] = __floats2half2_rn(v.x, v.y);
    d[1] = __floats2half2_rn(v.z, v.w);
}

// ---------------- embedding gather (fp16 out), token-offset variant ----------
__global__ void k_gather(const int* __restrict__ seq, const float* __restrict__ embed,
                         __half* __restrict__ out, int tbase) {
    int t = tbase + blockIdx.x;
    int v = seq[t];
    const float4* src = reinterpret_cast<const float4*>(embed + (size_t)v * H);
    float4 x = src[threadIdx.x];
    __half2* dst = reinterpret_cast<__half2*>(out + (size_t)t * H) + threadIdx.x * 2;
    dst[0] = __floats2half2_rn(x.x, x.y);
    dst[1] = __floats2half2_rn(x.z, x.w);
}

// ---------------- fp16 tensor GEMM ----------------
// MODE 0: +bias -> fp16; MODE 1: +bias+relu -> fp16; MODE 2: raw fp32 scatter [l][b][c]
template <int MODE>
__global__ void __launch_bounds__(256) k_gemm(const __half* __restrict__ A,
                                              const __half* __restrict__ W,
                                              const float* __restrict__ bias,
                                              void* __restrict__ Cv,
                                              int N, int K) {
    extern __shared__ char smem[];
    const uint32_t sb = smem_u32(smem);
    uint32_t a_off[STG], w_off[STG];
#pragma unroll
    for (int s = 0; s < STG; ++s) {
        a_off[s] = s * 2 * TILE_BYTES;
        w_off[s] = s * 2 * TILE_BYTES + TILE_BYTES;
    }

    const int tid = threadIdx.x;
    const int bm = blockIdx.y * TM;
    const int bn = blockIdx.x * TN;
    const int warp = tid >> 5, lane = tid & 31;
    const int wm = warp >> 2, wn = warp & 3;
    const int g = lane >> 2, tg = lane & 3;

    const int row = tid >> 1;
    const int h64 = tid & 1;
    const __half* Ag = A + (size_t)(bm + row) * K + h64 * 32;
    const __half* Wg = W + (size_t)(bn + row) * K + h64 * 32;
    uint32_t swz[4];
#pragma unroll
    for (int c = 0; c < 4; ++c) swz[c] = sw128(row * 128 + h64 * 64 + c * 16);

    float acc[4][4][4];
#pragma unroll
    for (int mi = 0; mi < 4; ++mi)
#pragma unroll
        for (int ni = 0; ni < 4; ++ni)
#pragma unroll
            for (int q = 0; q < 4; ++q) acc[mi][ni][q] = 0.f;

    auto issue_tile = [&](int st, int kt) {
#pragma unroll
        for (int c = 0; c < 4; ++c)
            cp16(sb + a_off[st] + swz[c], Ag + (size_t)kt * TKH + c * 8);
#pragma unroll
        for (int c = 0; c < 4; ++c)
            cp16(sb + w_off[st] + swz[c], Wg + (size_t)kt * TKH + c * 8);
        asm volatile("cp.async.commit_group;" ::: "memory");
    };

    const int a_r = lane & 15;
    const int a_cb = (lane >> 4) * 16;
    const int b_r = lane & 7;
    const int b_cb = ((lane >> 3) & 1) * 16;

    auto mma_pass = [&](int buf) {
#pragma unroll
        for (int ak = 0; ak < 4; ++ak) {
            const int kb = ak * 32;
            uint32_t afrag[4][4];
#pragma unroll
            for (int mi = 0; mi < 4; ++mi) {
                uint32_t addr = sb + a_off[buf] +
                    sw128((uint32_t)(wm * 64 + mi * 16 + a_r) * 128 + kb + a_cb);
                ldsm_x4(afrag[mi][0], afrag[mi][1], afrag[mi][2], afrag[mi][3], addr);
            }
            uint32_t bfrag[4][2];
#pragma unroll
            for (int ni = 0; ni < 4; ++ni) {
                uint32_t addr = sb + w_off[buf] +
                    sw128((uint32_t)(wn * 32 + ni * 8 + b_r) * 128 + kb + b_cb);
                ldsm_x2(bfrag[ni][0], bfrag[ni][1], addr);
            }
#pragma unroll
            for (int mi = 0; mi < 4; ++mi)
#pragma unroll
                for (int ni = 0; ni < 4; ++ni)
                    mma_f16(acc[mi][ni], afrag[mi], bfrag[ni]);
        }
    };

    const int NPASS = K / TKH;
    issue_tile(0, 0);
    issue_tile(1, 1);

    int p = 0;
    for (; p < NPASS - 1; ++p) {
        asm volatile("cp.async.wait_group 1;" ::: "memory");
        __syncthreads();
        if (p + 2 < NPASS) issue_tile((p + 2) % STG, p + 2);
        mma_pass(p % STG);
    }
    asm volatile("cp.async.wait_group 0;" ::: "memory");
    __syncthreads();
    mma_pass(p % STG);

#pragma unroll
    for (int mi = 0; mi < 4; ++mi) {
#pragma unroll
        for (int half = 0; half < 2; ++half) {
            int r = bm + wm * 64 + mi * 16 + g + half * 8;
#pragma unroll
            for (int ni = 0; ni < 4; ++ni) {
                int col = bn + wn * 32 + ni * 8 + tg * 2;
                float x = acc[mi][ni][half * 2 + 0];
                float y = acc[mi][ni][half * 2 + 1];
                if (MODE == 2) {
                    int b_ = r >> 10, l_ = r & 1023;
                    float* dst = (float*)Cv + ((size_t)l_ * B + b_) * HALF + col;
                    *reinterpret_cast<float2*>(dst) = make_float2(x, y);
                } else {
                    x += bias[col];
                    y += bias[col + 1];
                    if (MODE == 1) { x = fmaxf(x, 0.f); y = fmaxf(y, 0.f); }
                    __half* dst = (__half*)Cv + (size_t)r * N + col;
                    *reinterpret_cast<__half2*>(dst) = __floats2half2_rn(x, y);
                }
            }
        }
    }
}

// ---------------- residual + LayerNorm (warp per row; fp16 in/out) ----------------
__global__ void k_ln(const __half* __restrict__ y2, const __half* __restrict__ h0,
                     const float* __restrict__ gamma, const float* __restrict__ beta,
                     __half* __restrict__ out) {
    int warp = threadIdx.x >> 5, lane = threadIdx.x & 31;
    int row = blockIdx.x * 8 + warp;
    const __half2* a = reinterpret_cast<const __half2*>(y2 + (size_t)row * H);
    const __half2* hb = reinterpret_cast<const __half2*>(h0 + (size_t)row * H);
    float x[16];
    float s = 0.f, s2 = 0.f;
#pragma unroll
    for (int i = 0; i < 4; ++i) {
        int idx = (lane + i * 32) * 2;
        float2 u0 = __half22float2(a[idx]);
        float2 u1 = __half22float2(a[idx + 1]);
        float2 v0 = __half22float2(hb[idx]);
        float2 v1 = __half22float2(hb[idx + 1]);
        float t0 = u0.x + v0.x, t1 = u0.y + v0.y, t2 = u1.x + v1.x, t3 = u1.y + v1.y;
        x[i * 4 + 0] = t0; x[i * 4 + 1] = t1; x[i * 4 + 2] = t2; x[i * 4 + 3] = t3;
        s += t0 + t1 + t2 + t3;
        s2 += t0 * t0 + t1 * t1 + t2 * t2 + t3 * t3;
    }
#pragma unroll
    for (int off = 16; off > 0; off >>= 1) {
        s += __shfl_xor_sync(0xffffffffu, s, off);
        s2 += __shfl_xor_sync(0xffffffffu, s2, off);
    }
    float mu = s * (1.f / H);
    float var = s2 * (1.f / H) - mu * mu;
    float rstd = rsqrtf(var + EPS_LN_C);
    __half2* o = reinterpret_cast<__half2*>(out + (size_t)row * H);
    const float4* g4 = reinterpret_cast<const float4*>(gamma);
    const float4* b4 = reinterpret_cast<const float4*>(beta);
#pragma unroll
    for (int i = 0; i < 4; ++i) {
        float4 gg = __ldg(g4 + lane + i * 32);
        float4 bb = __ldg(b4 + lane + i * 32);
        float r0 = (x[i * 4 + 0] - mu) * rstd * gg.x + bb.x;
        float r1 = (x[i * 4 + 1] - mu) * rstd * gg.y + bb.y;
        float r2 = (x[i * 4 + 2] - mu) * rstd * gg.z + bb.z;
        float r3 = (x[i * 4 + 3] - mu) * rstd * gg.w + bb.w;
        o[(lane + i * 32) * 2] = __floats2half2_rn(r0, r1);
        o[(lane + i * 32) * 2 + 1] = __floats2half2_rn(r2, r3);
    }
}

// ---------------- Gram precompute (per m-half): one warp per (b,kblk) --------
__global__ void __launch_bounds__(32) k_gram(const float* __restrict__ kn_m,
                                             float* __restrict__ gram_m) {
    const int bx = blockIdx.x;
    const int b = bx / NBLK;
    const int kblk = bx - b * NBLK;
    const int lane = threadIdx.x;
    const float* kn = kn_m + b * HALF;
    const int t0 = 7 + 8 * kblk;
    const int STRD = B * HALF;

    float k8[8][8];
#pragma unroll
    for (int j = 0; j < 8; ++j) {
        const float4* p = reinterpret_cast<const float4*>(
            kn + (size_t)(t0 + j) * STRD + lane * 8);
        float4 u = __ldg(p), w = __ldg(p + 1);
        k8[j][0] = u.x; k8[j][1] = u.y; k8[j][2] = u.z; k8[j][3] = u.w;
        k8[j][4] = w.x; k8[j][5] = w.y; k8[j][6] = w.z; k8[j][7] = w.w;
    }
    float red[GSZ];
#pragma unroll
    for (int q = 0; q < GSZ; ++q) red[q] = 0.f;
#pragma unroll
    for (int e = 0; e < 8; ++e) {
        int p = 0;
#pragma unroll
        for (int j = 0; j < 8; ++j) {
#pragma unroll
            for (int i = j + 1; i < 8; ++i) {
                red[p] += k8[j][e] * k8[i][e];
                ++p;
            }
        }
#pragma unroll
        for (int j = 0; j < 8; ++j) red[28 + j] += k8[j][e] * k8[j][e];
    }
#pragma unroll
    for (int off = 16; off > 0; off >>= 1)
#pragma unroll
        for (int q = 0; q < GSZ; ++q)
            red[q] += __shfl_xor_sync(0xffffffffu, red[q], off);

    if (lane == 0) {
        float iv[8];
#pragma unroll
        for (int j = 0; j < 8; ++j)
            iv[j] = 1.f / fmaxf(sqrtf(red[28 + j]), EPS_NORM_C);
        float o[GSZ];
        int p = 0;
#pragma unroll
        for (int j = 0; j < 8; ++j)
#pragma unroll
            for (int i = j + 1; i < 8; ++i) {
                o[p] = ALPHA_C * red[p] * iv[j] * iv[i];
                ++p;
            }
#pragma unroll
        for (int j = 0; j < 8; ++j) o[28 + j] = iv[j];
        float4* dst = reinterpret_cast<float4*>(gram_m + (size_t)bx * GSZ);
#pragma unroll
        for (int q = 0; q < 9; ++q)
            dst[q] = make_float4(o[q * 4], o[q * 4 + 1], o[q * 4 + 2], o[q * 4 + 3]);
    }
}

// ---------------- EMA scan (per m-half): 8-step blocks, smem ring (1 warp) ----
#define GP(j, i) gb[(j) * 7 - (j) * ((j) - 1) / 2 + (i) - (j) - 1]

__global__ void __launch_bounds__(32) k_scan(const float* __restrict__ kn_m,
                                             const float* __restrict__ gram_m,
                                             float* __restrict__ cbuf, int moff) {
    const int lane = threadIdx.x;
    const int b = blockIdx.x;
    const float* kn = kn_m + b * HALF;
    const int STRD = B * HALF;

    __shared__ float stg[3][2048 + 64];

    auto prefetch = [&](int st, int kblk) {
        int t0 = 7 + 8 * kblk;
#pragma unroll
        for (int j = 0; j < 8; ++j) {
            const float* src = kn + (size_t)(t0 + j) * STRD + lane * 8;
            uint32_t dst = smem_u32(&stg[st][j * 256 + lane * 8]);
            cp16(dst, src);
            cp16(dst + 16, src + 4);
        }
        if (lane < 9)
            cp16(smem_u32(&stg[st][2048 + lane * 4]),
                 gram_m + (size_t)(b * NBLK + kblk) * GSZ + lane * 4);
        asm volatile("cp.async.commit_group;" ::: "memory");
    };

    float v[8], cac[8];
    {
        const float4* p = reinterpret_cast<const float4*>(
            kn + (size_t)(L - 1) * STRD + lane * 8);
        float4 u = __ldg(p), w = __ldg(p + 1);
        v[0] = u.x; v[1] = u.y; v[2] = u.z; v[3] = u.w;
        v[4] = w.x; v[5] = w.y; v[6] = w.z; v[7] = w.w;
    }
#pragma unroll
    for (int j = 0; j < 8; ++j) cac[j] = 0.f;

    prefetch(0, NBLK - 1);
    prefetch(1, NBLK - 2);
    prefetch(2, NBLK - 3);

    for (int it = 0; it < NBLK; ++it) {
        int st = it % 3;
        asm volatile("cp.async.wait_group 2;" ::: "memory");
        __syncwarp();
        float cur[8][8];
#pragma unroll
        for (int j = 0; j < 8; ++j) {
            float4 u = *reinterpret_cast<const float4*>(&stg[st][j * 256 + lane * 8]);
            float4 w = *reinterpret_cast<const float4*>(&stg[st][j * 256 + lane * 8 + 4]);
            cur[j][0] = u.x; cur[j][1] = u.y; cur[j][2] = u.z; cur[j][3] = u.w;
            cur[j][4] = w.x; cur[j][5] = w.y; cur[j][6] = w.z; cur[j][7] = w.w;
        }
        float gb[GSZ];
#pragma unroll
        for (int q = 0; q < 9; ++q) {
            float4 t = *reinterpret_cast<const float4*>(&stg[st][2048 + q * 4]);
            gb[q * 4] = t.x; gb[q * 4 + 1] = t.y; gb[q * 4 + 2] = t.z; gb[q * 4 + 3] = t.w;
        }
        __syncwarp();
        if (it + 3 < NBLK) prefetch(st, NBLK - 1 - (it + 3));

        float u[8];
#pragma unroll
        for (int j = 0; j < 8; ++j) {
            float d = cur[j][0] * v[0];
#pragma unroll
            for (int e = 1; e < 8; ++e) d += cur[j][e] * v[e];
            u[j] = d;
        }
#pragma unroll
        for (int off = 16; off > 0; off >>= 1)
#pragma unroll
            for (int j = 0; j < 8; ++j)
                u[j] += __shfl_xor_sync(0xffffffffu, u[j], off);

        float s7 = gb[35] * u[7];
        float s6 = gb[34] * u[6] - GP(6, 7) * s7;
        float s5 = gb[33] * u[5] - GP(5, 7) * s7 - GP(5, 6) * s6;
        float s4 = gb[32] * u[4] - GP(4, 7) * s7 - GP(4, 6) * s6 - GP(4, 5) * s5;
        float s3 = gb[31] * u[3] - GP(3, 7) * s7 - GP(3, 6) * s6 - GP(3, 5) * s5
                 - GP(3, 4) * s4;
        float s2 = gb[30] * u[2] - GP(2, 7) * s7 - GP(2, 6) * s6 - GP(2, 5) * s5
                 - GP(2, 4) * s4 - GP(2, 3) * s3;
        float s1 = gb[29] * u[1] - GP(1, 7) * s7 - GP(1, 6) * s6 - GP(1, 5) * s5
                 - GP(1, 4) * s4 - GP(1, 3) * s3 - GP(1, 2) * s2;
        float s0 = gb[28] * u[0] - GP(0, 7) * s7 - GP(0, 6) * s6 - GP(0, 5) * s5
                 - GP(0, 4) * s4 - GP(0, 3) * s3 - GP(0, 2) * s2 - GP(0, 1) * s1;

        float a0 = ALPHA_C * gb[28] * s0, a1 = ALPHA_C * gb[29] * s1;
        float a2 = ALPHA_C * gb[30] * s2, a3 = ALPHA_C * gb[31] * s3;
        float a4 = ALPHA_C * gb[32] * s4, a5 = ALPHA_C * gb[33] * s5;
        float a6 = ALPHA_C * gb[34] * s6, a7 = ALPHA_C * gb[35] * s7;

#pragma unroll
        for (int e = 0; e < 8; ++e) {
            float dv = cur[0][e] * a0 + cur[1][e] * a1 + cur[2][e] * a2 + cur[3][e] * a3
                     + cur[4][e] * a4 + cur[5][e] * a5 + cur[6][e] * a6 + cur[7][e] * a7;
            float dc = cur[0][e] * s0 + cur[1][e] * s1 + cur[2][e] * s2 + cur[3][e] * s3
                     + cur[4][e] * s4 + cur[5][e] * s5 + cur[6][e] * s6 + cur[7][e] * s7;
            v[e] -= dv;
            cac[e] += dc;
        }
    }

    for (int t = 6; t >= 0; --t) {
        float kt[8];
        const float4* p = reinterpret_cast<const float4*>(kn + (size_t)t * STRD + lane * 8);
        float4 u = __ldg(p), w = __ldg(p + 1);
        kt[0] = u.x; kt[1] = u.y; kt[2] = u.z; kt[3] = u.w;
        kt[4] = w.x; kt[5] = w.y; kt[6] = w.z; kt[7] = w.w;
        float du = 0.f, dg = 0.f;
#pragma unroll
        for (int j = 0; j < 8; ++j) { du += kt[j] * v[j]; dg += kt[j] * kt[j]; }
#pragma unroll
        for (int off = 16; off > 0; off >>= 1) {
            du += __shfl_xor_sync(0xffffffffu, du, off);
            dg += __shfl_xor_sync(0xffffffffu, dg, off);
        }
        float inv = 1.f / fmaxf(sqrtf(dg), EPS_NORM_C);
        float s = du * inv;
        float av = ALPHA_C * inv * s;
#pragma unroll
        for (int j = 0; j < 8; ++j) {
            cac[j] += kt[j] * s;
            v[j] -= kt[j] * av;
        }
    }

    float* out = cbuf + b * H + moff + lane * 8;
#pragma unroll
    for (int j = 0; j < 8; ++j) out[j] = ALPHA_C * cac[j];
}

// ---------------- r = c @ rp_w^T + rp_b ----------------
__global__ void k_rp(const float* __restrict__ c, const float* __restrict__ W,
                     const float* __restrict__ bias, float* __restrict__ r) {
    __shared__ float cs[B * (H + 1)];
    for (int i = threadIdx.x; i < B * H; i += 256) {
        int bb = i >> 9, hh = i & 511;
        cs[bb * (H + 1) + hh] = c[i];
    }
    __syncthreads();
    int g = blockIdx.x * 16 + (threadIdx.x >> 4);
    int b = threadIdx.x & 15;
    const float* w = W + (size_t)g * H;
    const float* cb = &cs[b * (H + 1)];
    float acc = 0.f;
    for (int h = 0; h < H; h += 4) {
        float4 wv = __ldg(reinterpret_cast<const float4*>(w + h));
        acc += cb[h] * wv.x + cb[h + 1] * wv.y + cb[h + 2] * wv.z + cb[h + 3] * wv.w;
    }
    r[b * H + g] = acc + bias[g];
}

// ---------------- logits via tensor cores ----------------
__global__ void __launch_bounds__(128) k_outt(const float* __restrict__ r,
                                              const __half* __restrict__ Wh,
                                              const float* __restrict__ bias,
                                              float* __restrict__ out) {
    extern __shared__ char smem[];
    __half* r_s = reinterpret_cast<__half*>(smem);
    const uint32_t sb = smem_u32(smem);
    const int tid = threadIdx.x;
    const int warp = tid >> 5, lane = tid & 31;
    const int bn = blockIdx.x * ONT;
    const int g = lane >> 2, tg = lane & 3;

#pragma unroll
    for (int j = 0; j < 16; ++j) {
        int f = tid + j * 128;
        float4 v = __ldg(reinterpret_cast<const float4*>(r) + f);
        int row = (f * 4) >> 9, col = (f * 4) & 511;
        __half2* d = reinterpret_cast<__half2*>(r_s + row * RS_STRIDE + col);
        d[0] = __floats2half2_rn(v.x, v.y);
        d[1] = __floats2half2_rn(v.z, v.w);
    }

    auto wtile = [&](int st, int kt) {
#pragma unroll
        for (int rr = 0; rr < 2; ++rr) {
            int row = rr * 128 + tid;
            const __half* s = Wh + (size_t)(bn + row) * H + kt * TKH;
            uint32_t base = sb + WT_OFF + st * WT_TILE;
#pragma unroll
            for (int c = 0; c < 8; ++c)
                cp16(base + sw128((uint32_t)row * 128 + c * 16), s + c * 8);
        }
        asm volatile("cp.async.commit_group;" ::: "memory");
    };

    float acc[8][4];
#pragma unroll
    for (int ni = 0; ni < 8; ++ni)
#pragma unroll
        for (int q = 0; q < 4; ++q) acc[ni][q] = 0.f;

    auto opass = [&](int buf, int kt) {
#pragma unroll
        for (int ak = 0; ak < 4; ++ak) {
            uint32_t af[4];
            uint32_t aaddr = sb + (uint32_t)((lane & 15) * RS_STRIDE * 2 +
                                             kt * 128 + ak * 32 + (lane >> 4) * 16);
            ldsm_x4(af[0], af[1], af[2], af[3], aaddr);
            uint32_t bf[8][2];
#pragma unroll
            for (int ni = 0; ni < 8; ++ni) {
                uint32_t addr = sb + WT_OFF + buf * WT_TILE +
                    sw128((uint32_t)(warp * 64 + ni * 8 + (lane & 7)) * 128 + ak * 32 +
                          ((lane >> 3) & 1) * 16);
                ldsm_x2(bf[ni][0], bf[ni][1], addr);
            }
#pragma unroll
            for (int ni = 0; ni < 8; ++ni)
                mma_f16(acc[ni], af, bf[ni]);
        }
    };

    const int NP = H / TKH;   // 8
    wtile(0, 0);
    wtile(1, 1);
    int p = 0;
    for (; p < NP - 1; ++p) {
        asm volatile("cp.async.wait_group 1;" ::: "memory");
        __syncthreads();
        if (p + 2 < NP) wtile((p + 2) % 3, p + 2);
        opass(p % 3, p);
    }
    asm volatile("cp.async.wait_group 0;" ::: "memory");
    __syncthreads();
    opass(p % 3, p);

#pragma unroll
    for (int ni = 0; ni < 8; ++ni) {
        int col = bn + warp * 64 + ni * 8 + tg * 2;
        float bx = __ldg(bias + col);
        float by = __ldg(bias + col + 1);
#pragma unroll
        for (int half = 0; half < 2; ++half) {
            int b = g + half * 8;
            float x = acc[ni][half * 2 + 0] + bx;
            float y = acc[ni][half * 2 + 1] + by;
            *reinterpret_cast<float2*>(out + (size_t)b * V + col) = make_float2(x, y);
        }
    }
}

// ---------------- launch: token-laddered trunk + forked tails ----------------
extern "C" void kernel_launch(void* const* d_in, const int* in_sizes, int n_in,
                              void* d_out, int out_size) {
    const int*   seq   = (const int*)d_in[0];
    const float* embed = (const float*)d_in[1];
    const float* ff_w1 = (const float*)d_in[2];
    const float* ff_b1 = (const float*)d_in[3];
    const float* ff_w2 = (const float*)d_in[4];
    const float* ff_b2 = (const float*)d_in[5];
    const float* gamma = (const float*)d_in[6];
    const float* beta  = (const float*)d_in[7];
    const float* sem_w = (const float*)d_in[8];
    const float* epi_w = (const float*)d_in[9];
    const float* rp_w  = (const float*)d_in[10];
    const float* rp_b  = (const float*)d_in[11];
    const float* out_w = (const float*)d_in[12];
    const float* out_b = (const float*)d_in[13];
    float* out = (float*)d_out;

    __half *h0h, *ff1h, *y2h, *hh, *w1h, *w2h, *wch, *owh;
    float *kn, *gr, *c, *r;
    cudaGetSymbolAddress((void**)&h0h,  g_h0h);
    cudaGetSymbolAddress((void**)&ff1h, g_ff1h);
    cudaGetSymbolAddress((void**)&y2h,  g_y2h);
    cudaGetSymbolAddress((void**)&hh,   g_hh);
    cudaGetSymbolAddress((void**)&kn,   g_kn);
    cudaGetSymbolAddress((void**)&gr,   g_gram);
    cudaGetSymbolAddress((void**)&c,    g_c);
    cudaGetSymbolAddress((void**)&r,    g_r);
    cudaGetSymbolAddress((void**)&w1h,  g_w1h);
    cudaGetSymbolAddress((void**)&w2h,  g_w2h);
    cudaGetSymbolAddress((void**)&wch,  g_wch);
    cudaGetSymbolAddress((void**)&owh,  g_owh);

    static cudaStream_t sA = nullptr, sB = nullptr;
    static cudaEvent_t e0 = nullptr, evGA = nullptr, evGB = nullptr, eW = nullptr,
                       evG1A = nullptr, evG1B = nullptr, ev0A = nullptr, ev0B = nullptr,
                       evLNA = nullptr, evLNB = nullptr, evS = nullptr;
    if (sA == nullptr) {
        cudaStreamCreateWithFlags(&sA, cudaStreamNonBlocking);
        cudaStreamCreateWithFlags(&sB, cudaStreamNonBlocking);
        cudaEventCreateWithFlags(&e0, cudaEventDisableTiming);
        cudaEventCreateWithFlags(&evGA, cudaEventDisableTiming);
        cudaEventCreateWithFlags(&evGB, cudaEventDisableTiming);
        cudaEventCreateWithFlags(&eW, cudaEventDisableTiming);
        cudaEventCreateWithFlags(&evG1A, cudaEventDisableTiming);
        cudaEventCreateWithFlags(&evG1B, cudaEventDisableTiming);
        cudaEventCreateWithFlags(&ev0A, cudaEventDisableTiming);
        cudaEventCreateWithFlags(&ev0B, cudaEventDisableTiming);
        cudaEventCreateWithFlags(&evLNA, cudaEventDisableTiming);
        cudaEventCreateWithFlags(&evLNB, cudaEventDisableTiming);
        cudaEventCreateWithFlags(&evS, cudaEventDisableTiming);
        cudaFuncSetAttribute(k_gemm<0>, cudaFuncAttributeMaxDynamicSharedMemorySize, SMEM_H);
        cudaFuncSetAttribute(k_gemm<1>, cudaFuncAttributeMaxDynamicSharedMemorySize, SMEM_H);
        cudaFuncSetAttribute(k_gemm<2>, cudaFuncAttributeMaxDynamicSharedMemorySize, SMEM_H);
        cudaFuncSetAttribute(k_outt, cudaFuncAttributeMaxDynamicSharedMemorySize, SMEM_OUT);
    }

    const size_t knoff = (size_t)L * B * HALF;
    const size_t groff = (size_t)16 * NBLK * GSZ;

    // ---- prep stream sA: gather halves, then remaining weight conversions
    cudaEventRecord(e0, 0);
    cudaStreamWaitEvent(sA, e0, 0);
    k_gather<<<TOKH, 128, 0, sA>>>(seq, embed, h0h, 0);
    cudaEventRecord(evGA, sA);
    k_gather<<<TOKH, 128, 0, sA>>>(seq, embed, h0h, TOKH);
    cudaEventRecord(evGB, sA);
    k_round_rest<<<768 + (int)(((size_t)V * H) / 1024), 256, 0, sA>>>(
        ff_w2, sem_w, epi_w, out_w, w2h, wch, owh);
    cudaEventRecord(eW, sA);

    // ---- trunk, token-laddered across D and sB
    k_round_w1<<<512, 256>>>(ff_w1, w1h);
    cudaStreamWaitEvent(0, evGA, 0);
    k_gemm<1><<<dim3(2 * H / TN, TOKH / TM), 256, SMEM_H>>>(
        h0h, w1h, ff_b1, ff1h, 2 * H, H);
    cudaEventRecord(evG1A, 0);
    cudaStreamWaitEvent(0, evGB, 0);
    k_gemm<1><<<dim3(2 * H / TN, TOKH / TM), 256, SMEM_H>>>(
        h0h + (size_t)TOKH * H, w1h, ff_b1, ff1h + (size_t)TOKH * 2 * H, 2 * H, H);
    cudaEventRecord(evG1B, 0);

    cudaStreamWaitEvent(sB, evG1A, 0);
    cudaStreamWaitEvent(sB, eW, 0);
    k_gemm<0><<<dim3(H / TN, TOKH / TM), 256, SMEM_H, sB>>>(
        ff1h, w2h, ff_b2, y2h, H, 2 * H);
    cudaEventRecord(ev0A, sB);
    cudaStreamWaitEvent(sB, evG1B, 0);
    k_gemm<0><<<dim3(H / TN, TOKH / TM), 256, SMEM_H, sB>>>(
        ff1h + (size_t)TOKH * 2 * H, w2h, ff_b2, y2h + (size_t)TOKH * H, H, 2 * H);
    cudaEventRecord(ev0B, sB);

    cudaStreamWaitEvent(0, ev0A, 0);
    k_ln<<<TOKH / 8, 256>>>(y2h, h0h, gamma, beta, hh);
    cudaEventRecord(evLNA, 0);
    cudaStreamWaitEvent(0, ev0B, 0);
    k_ln<<<TOKH / 8, 256>>>(y2h + (size_t)TOKH * H, h0h + (size_t)TOKH * H,
                            gamma, beta, hh + (size_t)TOKH * H);
    cudaEventRecord(evLNB, 0);

    // ---- tails: sem chain on sB, epi chain on D (both need full hh)
    cudaStreamWaitEvent(sB, evLNA, 0);
    cudaStreamWaitEvent(sB, evLNB, 0);
    k_gemm<2><<<dim3(HALF / TN, TOK / TM), 256, SMEM_H, sB>>>(hh, wch, nullptr, kn, HALF, H);
    k_gram<<<16 * NBLK, 32, 0, sB>>>(kn, gr);
    k_scan<<<16, 32, 0, sB>>>(kn, gr, c, 0);
    cudaEventRecord(evS, sB);

    k_gemm<2><<<dim3(HALF / TN, TOK / TM), 256, SMEM_H>>>(hh, wch + (size_t)HALF * H,
                                                          nullptr, kn + knoff, HALF, H);
    k_gram<<<16 * NBLK, 32>>>(kn + knoff, gr + groff);
    k_scan<<<16, 32>>>(kn + knoff, gr + groff, c, HALF);

    // ---- join and finish
    cudaStreamWaitEvent(0, evS, 0);
    k_rp<<<H / 16, 256>>>(c, rp_w, rp_b, r);
    k_outt<<<V / ONT, 128, SMEM_OUT>>>(r, owh, out_b, out);
}